// round 13
// baseline (speedup 1.0000x reference)
#include <cuda_runtime.h>
#include <cuda_bf16.h>
#include <cstdint>
#include <math.h>

// Problem constants (fixed shapes from setup_inputs)
#define BB   8
#define NN   4096      // 64*64
#define DD   256
#define NH   8
#define NP   4
#define HD   32
#define MM   (BB*NN)   // 32768 rows
#define NCAT 384       // 256 (v) + 64 (off) + 32 (attw) + 32 pad

#define TILE_PX  16
#define WIN      20                         // 16 + 2*2 halo

// ---------------- scratch (device globals; no allocations allowed) ----------
__device__ float g_y[(size_t)MM * NCAT];          // stage-1 output: v | off | attw
__device__ float g_bcat[NCAT];                    // packed stage-1 bias
__device__ __nv_bfloat16 g_xh[(size_t)MM * DD];   // x split hi
__device__ __nv_bfloat16 g_xl[(size_t)MM * DD];   // x split lo
__device__ __nv_bfloat16 g_midh[(size_t)MM * DD]; // sampled output split hi
__device__ __nv_bfloat16 g_midl[(size_t)MM * DD]; // sampled output split lo
__device__ __nv_bfloat16 g_w1h[DD * NCAT];        // [k][n] stage-1 weights hi
__device__ __nv_bfloat16 g_w1l[DD * NCAT];
__device__ __nv_bfloat16 g_w2h[DD * DD];          // [k][n] proj weights hi
__device__ __nv_bfloat16 g_w2l[DD * DD];

// =================== helpers ===================
__device__ __forceinline__ uint32_t smem_to_u32(const void* p) {
    uint32_t a;
    asm("{ .reg .u64 t; cvta.to.shared.u64 t, %1; cvt.u32.u64 %0, t; }" : "=r"(a) : "l"(p));
    return a;
}
__device__ __forceinline__ void split_bf16(float w, __nv_bfloat16& h, __nv_bfloat16& l) {
    h = __float2bfloat16_rn(w);
    l = __float2bfloat16_rn(w - __bfloat162float(h));
}
__device__ __forceinline__ void cp_async16(uint32_t dst, const void* src) {
    asm volatile("{ .reg .u64 g; cvta.to.global.u64 g, %1; cp.async.cg.shared.global [%0], [g], 16; }"
                 :: "r"(dst), "l"(src));
}
__device__ __forceinline__ void cp_commit() {
    asm volatile("cp.async.commit_group;");
}
__device__ __forceinline__ void ldsm_x4(uint32_t (&r)[4], uint32_t addr) {
    asm volatile("ldmatrix.sync.aligned.m8n8.x4.shared.b16 {%0,%1,%2,%3}, [%4];"
                 : "=r"(r[0]), "=r"(r[1]), "=r"(r[2]), "=r"(r[3]) : "r"(addr));
}
__device__ __forceinline__ void ldsm_x4t(uint32_t (&r)[4], uint32_t addr) {
    asm volatile("ldmatrix.sync.aligned.m8n8.x4.trans.shared.b16 {%0,%1,%2,%3}, [%4];"
                 : "=r"(r[0]), "=r"(r[1]), "=r"(r[2]), "=r"(r[3]) : "r"(addr));
}
__device__ __forceinline__ void mma_bf16(float (&c)[4], const uint32_t (&a)[4], const uint32_t (&b)[2]) {
    asm volatile("mma.sync.aligned.m16n8k16.row.col.f32.bf16.bf16.f32 "
                 "{%0,%1,%2,%3}, {%4,%5,%6,%7}, {%8,%9}, {%0,%1,%2,%3};"
                 : "+f"(c[0]), "+f"(c[1]), "+f"(c[2]), "+f"(c[3])
                 : "r"(a[0]), "r"(a[1]), "r"(a[2]), "r"(a[3]), "r"(b[0]), "r"(b[1]));
}

// =================== pack kernels (proven R10) ===================
__global__ void pack_x_kernel(const float* __restrict__ x)
{
    int idx = blockIdx.x * blockDim.x + threadIdx.x;   // over MM*DD/4
    if (idx < MM * DD / 4) {
        float4 v = reinterpret_cast<const float4*>(x)[idx];
        __nv_bfloat16 h0, l0, h1, l1, h2, l2, h3, l3;
        split_bf16(v.x, h0, l0); split_bf16(v.y, h1, l1);
        split_bf16(v.z, h2, l2); split_bf16(v.w, h3, l3);
        uint2 ph, pl;
        ph.x = ((uint32_t)__bfloat16_as_ushort(h1) << 16) | __bfloat16_as_ushort(h0);
        ph.y = ((uint32_t)__bfloat16_as_ushort(h3) << 16) | __bfloat16_as_ushort(h2);
        pl.x = ((uint32_t)__bfloat16_as_ushort(l1) << 16) | __bfloat16_as_ushort(l0);
        pl.y = ((uint32_t)__bfloat16_as_ushort(l3) << 16) | __bfloat16_as_ushort(l2);
        reinterpret_cast<uint2*>(g_xh)[idx] = ph;
        reinterpret_cast<uint2*>(g_xl)[idx] = pl;
    }
}

__global__ void pack_w_kernel(const float* __restrict__ qkv_w, const float* __restrict__ qkv_b,
                              const float* __restrict__ off_w, const float* __restrict__ off_b,
                              const float* __restrict__ attw_w, const float* __restrict__ attw_b,
                              const float* __restrict__ proj_w)
{
    int idx = blockIdx.x * blockDim.x + threadIdx.x;
    if (idx < DD * NCAT) {
        int k = idx / NCAT, n = idx % NCAT;
        float w;
        if (n < 256)      w = qkv_w[k * 768 + 512 + n];
        else if (n < 320) w = off_w[k * 64 + (n - 256)];
        else if (n < 352) w = attw_w[k * 32 + (n - 320)];
        else              w = 0.0f;
        __nv_bfloat16 h, l; split_bf16(w, h, l);
        g_w1h[idx] = h; g_w1l[idx] = l;
    }
    int idx2 = idx - DD * NCAT;
    if (idx2 >= 0 && idx2 < DD * DD) {
        __nv_bfloat16 h, l; split_bf16(proj_w[idx2], h, l);
        g_w2h[idx2] = h; g_w2l[idx2] = l;
    }
    if (idx < NCAT) {
        float bv;
        if (idx < 256)      bv = qkv_b[512 + idx];
        else if (idx < 320) bv = off_b[idx - 256];
        else if (idx < 352) bv = attw_b[idx - 320];
        else                bv = 0.0f;
        g_bcat[idx] = bv;
    }
}

// =================== mma.sync bf16x3 GEMM (proven R10 config) ===============
#define A_ROW_B   80
#define B_ROW_B   144
#define SM_A_SZ   10240                     // 128*80
#define SM_B_OFF  20480                     // 2 * SM_A_SZ
#define SM_B_SZ   4608                      // 32*144
#define SM_STAGE  29696                     // 20480 + 2*4608
#define N_STAGE   3
#define SMEM_GEMM_SZ (N_STAGE * SM_STAGE)   // 89088

__device__ __forceinline__ void mma_gemm_body(const __nv_bfloat16* __restrict__ Ah,
                                              const __nv_bfloat16* __restrict__ Al,
                                              const __nv_bfloat16* __restrict__ Bh,
                                              const __nv_bfloat16* __restrict__ Bl,
                                              const float* __restrict__ bias,
                                              float* __restrict__ C, int Nw)
{
    extern __shared__ char smem[];
    const uint32_t sm = smem_to_u32(smem);
    const int tid = threadIdx.x;
    const int lane = tid & 31, wid = tid >> 5;
    const int warp_m = wid >> 1, warp_n = wid & 1;
    const int m0 = blockIdx.y * 128, n0 = blockIdx.x * 64;

    const __nv_bfloat16* a_src[4]; uint32_t a_dst[4];
#pragma unroll
    for (int i = 0; i < 4; ++i) {
        int c = tid + i * 256;
        int mat = c >> 9, cc = c & 511, row = cc >> 2, kc = cc & 3;
        a_src[i] = (mat ? Al : Ah) + (size_t)(m0 + row) * DD + kc * 8;
        a_dst[i] = sm + mat * SM_A_SZ + row * A_ROW_B + kc * 16;
    }
    const __nv_bfloat16* b_src[2]; uint32_t b_dst[2];
#pragma unroll
    for (int j = 0; j < 2; ++j) {
        int c = tid + j * 256;
        int mat = c >> 8, cc = c & 255, row = cc >> 3, nc = cc & 7;
        b_src[j] = (mat ? Bl : Bh) + (size_t)row * Nw + n0 + nc * 8;
        b_dst[j] = sm + SM_B_OFF + mat * SM_B_SZ + row * B_ROW_B + nc * 16;
    }

    float acc[2][4][4];
#pragma unroll
    for (int mt = 0; mt < 2; ++mt)
#pragma unroll
        for (int nt = 0; nt < 4; ++nt)
#pragma unroll
            for (int e = 0; e < 4; ++e) acc[mt][nt][e] = 0.0f;

    auto prefetch = [&](int s, int buf) {
        uint32_t bo = (uint32_t)buf * SM_STAGE;
#pragma unroll
        for (int i = 0; i < 4; ++i) cp_async16(a_dst[i] + bo, a_src[i] + s * 32);
#pragma unroll
        for (int j = 0; j < 2; ++j) cp_async16(b_dst[j] + bo, b_src[j] + (size_t)s * 32 * Nw);
        cp_commit();
    };

    prefetch(0, 0);
    prefetch(1, 1);
    int buf = 0;
    for (int s = 0; s < 8; ++s) {
        if (s < 7) asm volatile("cp.async.wait_group 1;");
        else       asm volatile("cp.async.wait_group 0;");
        __syncthreads();
        if (s + 2 < 8) prefetch(s + 2, (s + 2) % 3);

        uint32_t base = sm + (uint32_t)buf * SM_STAGE;
#pragma unroll
        for (int k16 = 0; k16 < 2; ++k16) {
            const int kk = k16 * 16;
            uint32_t ah[2][4], al[2][4];
            const int rA = lane & 15, cA = kk + ((lane >> 4) << 3);
#pragma unroll
            for (int mt = 0; mt < 2; ++mt) {
                uint32_t ad = base + (warp_m * 32 + mt * 16 + rA) * A_ROW_B + cA * 2;
                ldsm_x4(ah[mt], ad);
                ldsm_x4(al[mt], ad + SM_A_SZ);
            }
            uint32_t bh[4][2], bl[4][2];
            const int rB = kk + (lane & 15);
            const int cB = warp_n * 32 + ((lane >> 4) << 3);
#pragma unroll
            for (int ntp = 0; ntp < 2; ++ntp) {
                uint32_t bd = base + SM_B_OFF + rB * B_ROW_B + (cB + ntp * 16) * 2;
                uint32_t t4[4];
                ldsm_x4t(t4, bd);
                bh[2 * ntp][0] = t4[0]; bh[2 * ntp][1] = t4[1];
                bh[2 * ntp + 1][0] = t4[2]; bh[2 * ntp + 1][1] = t4[3];
                ldsm_x4t(t4, bd + SM_B_SZ);
                bl[2 * ntp][0] = t4[0]; bl[2 * ntp][1] = t4[1];
                bl[2 * ntp + 1][0] = t4[2]; bl[2 * ntp + 1][1] = t4[3];
            }
#pragma unroll
            for (int mt = 0; mt < 2; ++mt)
#pragma unroll
                for (int nt = 0; nt < 4; ++nt)
                    mma_bf16(acc[mt][nt], ah[mt], bh[nt]);
#pragma unroll
            for (int mt = 0; mt < 2; ++mt)
#pragma unroll
                for (int nt = 0; nt < 4; ++nt)
                    mma_bf16(acc[mt][nt], al[mt], bh[nt]);
#pragma unroll
            for (int mt = 0; mt < 2; ++mt)
#pragma unroll
                for (int nt = 0; nt < 4; ++nt)
                    mma_bf16(acc[mt][nt], ah[mt], bl[nt]);
        }
        buf = (buf + 1) % 3;
    }

    const int rbase = m0 + warp_m * 32 + (lane >> 2);
    const int cbase = n0 + warp_n * 32 + (lane & 3) * 2;
#pragma unroll
    for (int mt = 0; mt < 2; ++mt) {
#pragma unroll
        for (int nt = 0; nt < 4; ++nt) {
            int col = cbase + nt * 8;
            float b0 = bias[col], b1 = bias[col + 1];
            float2 v0 = make_float2(acc[mt][nt][0] + b0, acc[mt][nt][1] + b1);
            float2 v1 = make_float2(acc[mt][nt][2] + b0, acc[mt][nt][3] + b1);
            *reinterpret_cast<float2*>(C + (size_t)(rbase + mt * 16) * Nw + col) = v0;
            *reinterpret_cast<float2*>(C + (size_t)(rbase + mt * 16 + 8) * Nw + col) = v1;
        }
    }
}

__global__ __launch_bounds__(256, 2) void gemm1_kernel()
{
    mma_gemm_body(g_xh, g_xl, g_w1h, g_w1l, g_bcat, g_y, NCAT);
}

__global__ __launch_bounds__(256, 2) void gemm2_kernel(const float* __restrict__ proj_b,
                                                       float* __restrict__ out)
{
    mma_gemm_body(g_midh, g_midl, g_w2h, g_w2l, proj_b, out, DD);
}

// ---------------- deformable sampling: fused prep + gather ------------------
// One block per (b, h, 16x16 tile). Lane-parallel in-smem prep (R12), then
// gather with FOUR independent per-point accumulators (breaks the 16-FFMA
// serial chain; ILP x4).
#define PREP_STRIDE 24                       // floats per pixel (16B aligned)
#define SMEM_WIN_SZ (WIN * WIN * HD * 4)     // 51200
#define SMEM_SAMP_SZ (SMEM_WIN_SZ + 256 * PREP_STRIDE * 4)   // 75776

__global__ __launch_bounds__(256) void sample_kernel()
{
    extern __shared__ float vt[];            // window [400][32], then prep [256][24]
    float* prep = vt + WIN * WIN * HD;
    const int tid = threadIdx.x;
    const int lane = tid & 31, wid = tid >> 5;

    const int t = blockIdx.x;
    const int tile = t & 15;
    const int h = (t >> 4) & 7;
    const int b = t >> 7;
    const int tx0 = (tile & 3) * TILE_PX;
    const int ty0 = (tile >> 2) * TILE_PX;

    // ---- lane-parallel prep: pixel q = wid*32 + lane ----
    {
        int q = wid * 32 + lane;
        int py = q >> 4, px = q & 15;
        int n = (ty0 + py) * 64 + (tx0 + px);
        const float* yrow = g_y + (size_t)(b * NN + n) * NCAT;

        float4 o0 = *reinterpret_cast<const float4*>(yrow + 256 + h * 8);
        float4 o1 = *reinterpret_cast<const float4*>(yrow + 256 + h * 8 + 4);
        float4 av = *reinterpret_cast<const float4*>(yrow + 320 + h * 4);
        float offr[8] = {o0.x, o0.y, o0.z, o0.w, o1.x, o1.y, o1.z, o1.w};
        float aw[4] = {av.x, av.y, av.z, av.w};

        float mx = fmaxf(fmaxf(aw[0], aw[1]), fmaxf(aw[2], aw[3]));
        float s = 0.0f;
#pragma unroll
        for (int p = 0; p < NP; ++p) { aw[p] = __expf(aw[p] - mx); s += aw[p]; }
        float inv = 1.0f / s;

        float pxl = (float)px + 2.0f;
        float pyl = (float)py + 2.0f;

        int offs[4]; float4 w[4];
#pragma unroll
        for (int p = 0; p < NP; ++p) {
            float lgx = pxl + 2.0f * tanhf(offr[2 * p]);
            float lgy = pyl + 2.0f * tanhf(offr[2 * p + 1]);
            float x0f = floorf(lgx), y0f = floorf(lgy);
            float wx1 = lgx - x0f, wy1 = lgy - y0f;
            float wx0 = 1.0f - wx1, wy0 = 1.0f - wy1;
            float ap = aw[p] * inv;
            w[p].x = ap * wx0 * wy0;
            w[p].y = ap * wx1 * wy0;
            w[p].z = ap * wx0 * wy1;
            w[p].w = ap * wx1 * wy1;
            offs[p] = ((int)y0f * WIN + (int)x0f) * HD;
        }
        float* dst = prep + q * PREP_STRIDE;
        *reinterpret_cast<int4*>(dst) = make_int4(offs[0], offs[1], offs[2], offs[3]);
        *reinterpret_cast<float4*>(dst + 4)  = w[0];
        *reinterpret_cast<float4*>(dst + 8)  = w[1];
        *reinterpret_cast<float4*>(dst + 12) = w[2];
        *reinterpret_cast<float4*>(dst + 16) = w[3];
    }

    // ---- load 20x20x32 window (zero-filled at image borders) ----
    for (int p = wid; p < WIN * WIN; p += 8) {
        int py = p / WIN, px = p % WIN;
        int gy = ty0 - 2 + py, gx = tx0 - 2 + px;
        float v = 0.0f;
        if (gy >= 0 && gy < 64 && gx >= 0 && gx < 64)
            v = g_y[(size_t)(b * NN + gy * 64 + gx) * NCAT + h * HD + lane];
        vt[p * HD + lane] = v;
    }
    __syncthreads();

    const float* basep = vt + lane;

    // ---- main loop: warp w handles pixels [32w, 32w+32) ----
#pragma unroll 4
    for (int j = 0; j < 32; ++j) {
        int q = wid * 32 + j;
        const float* pp = prep + q * PREP_STRIDE;
        int4 off  = *reinterpret_cast<const int4*>(pp);
        float4 w0 = *reinterpret_cast<const float4*>(pp + 4);
        float4 w1 = *reinterpret_cast<const float4*>(pp + 8);
        float4 w2 = *reinterpret_cast<const float4*>(pp + 12);
        float4 w3 = *reinterpret_cast<const float4*>(pp + 16);

        const float* c0 = basep + off.x;
        const float* c1 = basep + off.y;
        const float* c2 = basep + off.z;
        const float* c3 = basep + off.w;

        // four INDEPENDENT accumulators (per point) — breaks the serial chain
        float a0 = w0.x * c0[0];
        float a1 = w1.x * c1[0];
        float a2 = w2.x * c2[0];
        float a3 = w3.x * c3[0];
        a0 = fmaf(w0.y, c0[HD], a0);
        a1 = fmaf(w1.y, c1[HD], a1);
        a2 = fmaf(w2.y, c2[HD], a2);
        a3 = fmaf(w3.y, c3[HD], a3);
        a0 = fmaf(w0.z, c0[WIN * HD], a0);
        a1 = fmaf(w1.z, c1[WIN * HD], a1);
        a2 = fmaf(w2.z, c2[WIN * HD], a2);
        a3 = fmaf(w3.z, c3[WIN * HD], a3);
        a0 = fmaf(w0.w, c0[WIN * HD + HD], a0);
        a1 = fmaf(w1.w, c1[WIN * HD + HD], a1);
        a2 = fmaf(w2.w, c2[WIN * HD + HD], a2);
        a3 = fmaf(w3.w, c3[WIN * HD + HD], a3);
        float acc = (a0 + a1) + (a2 + a3);

        int n = (ty0 + (q >> 4)) * 64 + (tx0 + (q & 15));
        size_t ofs = (size_t)(b * NN + n) * DD + h * HD + lane;
        __nv_bfloat16 hh, ll; split_bf16(acc, hh, ll);
        g_midh[ofs] = hh;
        g_midl[ofs] = ll;
    }
}

// ---------------- launch ----------------
extern "C" void kernel_launch(void* const* d_in, const int* in_sizes, int n_in,
                              void* d_out, int out_size)
{
    const float* x      = (const float*)d_in[0];
    const float* qkv_w  = (const float*)d_in[1];
    const float* qkv_b  = (const float*)d_in[2];
    const float* off_w  = (const float*)d_in[3];
    const float* off_b  = (const float*)d_in[4];
    const float* attw_w = (const float*)d_in[5];
    const float* attw_b = (const float*)d_in[6];
    const float* proj_w = (const float*)d_in[7];
    const float* proj_b = (const float*)d_in[8];
    float* out = (float*)d_out;

    cudaFuncSetAttribute(gemm1_kernel, cudaFuncAttributeMaxDynamicSharedMemorySize, SMEM_GEMM_SZ);
    cudaFuncSetAttribute(gemm2_kernel, cudaFuncAttributeMaxDynamicSharedMemorySize, SMEM_GEMM_SZ);
    cudaFuncSetAttribute(sample_kernel, cudaFuncAttributeMaxDynamicSharedMemorySize, SMEM_SAMP_SZ);

    // 1) split inputs/weights into bf16 hi/lo
    pack_x_kernel<<<(MM * DD / 4 + 255) / 256, 256>>>(x);
    pack_w_kernel<<<(DD * NCAT + DD * DD + 255) / 256, 256>>>(
        qkv_w, qkv_b, off_w, off_b, attw_w, attw_b, proj_w);

    // 2) stage-1 GEMM (mma.sync bf16x3): X[32768,256] @ Wcat[256,384] -> g_y
    gemm1_kernel<<<dim3(NCAT / 64, MM / 128), 256, SMEM_GEMM_SZ>>>();

    // 3) deformable sampling with fused in-smem prep + 4-way ILP gather
    sample_kernel<<<BB * NH * 16, 256, SMEM_SAMP_SZ>>>();

    // 4) output projection (mma.sync bf16x3): mid @ proj_w[256,256] + b -> out
    gemm2_kernel<<<dim3(DD / 64, MM / 128), 256, SMEM_GEMM_SZ>>>(proj_b, out);
}

// round 14
// speedup vs baseline: 1.1034x; 1.1034x over previous
#include <cuda_runtime.h>
#include <cuda_bf16.h>
#include <cstdint>
#include <math.h>

// Problem constants (fixed shapes from setup_inputs)
#define BB   8
#define NN   4096      // 64*64
#define DD   256
#define NH   8
#define NP   4
#define HD   32
#define MM   (BB*NN)   // 32768 rows
#define NCAT 384       // 256 (v) + 64 (off) + 32 (attw) + 32 pad

#define TILE_PX  16
#define WIN      20                         // 16 + 2*2 halo

// ---------------- scratch (device globals; no allocations allowed) ----------
__device__ float g_y[(size_t)MM * NCAT];          // stage-1 output: v | off | attw
__device__ float g_bcat[NCAT];                    // packed stage-1 bias
__device__ __nv_bfloat16 g_xh[(size_t)MM * DD];   // x split hi
__device__ __nv_bfloat16 g_xl[(size_t)MM * DD];   // x split lo
__device__ __nv_bfloat16 g_midh[(size_t)MM * DD]; // sampled output split hi
__device__ __nv_bfloat16 g_midl[(size_t)MM * DD]; // sampled output split lo
__device__ __nv_bfloat16 g_w1h[DD * NCAT];        // [k][n] stage-1 weights hi
__device__ __nv_bfloat16 g_w1l[DD * NCAT];
__device__ __nv_bfloat16 g_w2h[DD * DD];          // [k][n] proj weights hi
__device__ __nv_bfloat16 g_w2l[DD * DD];

// =================== helpers ===================
__device__ __forceinline__ uint32_t smem_to_u32(const void* p) {
    uint32_t a;
    asm("{ .reg .u64 t; cvta.to.shared.u64 t, %1; cvt.u32.u64 %0, t; }" : "=r"(a) : "l"(p));
    return a;
}
__device__ __forceinline__ void split_bf16(float w, __nv_bfloat16& h, __nv_bfloat16& l) {
    h = __float2bfloat16_rn(w);
    l = __float2bfloat16_rn(w - __bfloat162float(h));
}
__device__ __forceinline__ void cp_async16(uint32_t dst, const void* src) {
    asm volatile("{ .reg .u64 g; cvta.to.global.u64 g, %1; cp.async.cg.shared.global [%0], [g], 16; }"
                 :: "r"(dst), "l"(src));
}
// cp.async with dynamic src-size: bytes beyond sz are ZERO-FILLED (sz=0 -> all zeros)
__device__ __forceinline__ void cp_async16_z(uint32_t dst, const void* src, int sz) {
    asm volatile("{ .reg .u64 g; cvta.to.global.u64 g, %1; cp.async.cg.shared.global [%0], [g], 16, %2; }"
                 :: "r"(dst), "l"(src), "r"(sz));
}
__device__ __forceinline__ void cp_commit() {
    asm volatile("cp.async.commit_group;");
}
__device__ __forceinline__ void ldsm_x4(uint32_t (&r)[4], uint32_t addr) {
    asm volatile("ldmatrix.sync.aligned.m8n8.x4.shared.b16 {%0,%1,%2,%3}, [%4];"
                 : "=r"(r[0]), "=r"(r[1]), "=r"(r[2]), "=r"(r[3]) : "r"(addr));
}
__device__ __forceinline__ void ldsm_x4t(uint32_t (&r)[4], uint32_t addr) {
    asm volatile("ldmatrix.sync.aligned.m8n8.x4.trans.shared.b16 {%0,%1,%2,%3}, [%4];"
                 : "=r"(r[0]), "=r"(r[1]), "=r"(r[2]), "=r"(r[3]) : "r"(addr));
}
__device__ __forceinline__ void mma_bf16(float (&c)[4], const uint32_t (&a)[4], const uint32_t (&b)[2]) {
    asm volatile("mma.sync.aligned.m16n8k16.row.col.f32.bf16.bf16.f32 "
                 "{%0,%1,%2,%3}, {%4,%5,%6,%7}, {%8,%9}, {%0,%1,%2,%3};"
                 : "+f"(c[0]), "+f"(c[1]), "+f"(c[2]), "+f"(c[3])
                 : "r"(a[0]), "r"(a[1]), "r"(a[2]), "r"(a[3]), "r"(b[0]), "r"(b[1]));
}

// =================== pack kernels (proven R10) ===================
__global__ void pack_x_kernel(const float* __restrict__ x)
{
    int idx = blockIdx.x * blockDim.x + threadIdx.x;   // over MM*DD/4
    if (idx < MM * DD / 4) {
        float4 v = reinterpret_cast<const float4*>(x)[idx];
        __nv_bfloat16 h0, l0, h1, l1, h2, l2, h3, l3;
        split_bf16(v.x, h0, l0); split_bf16(v.y, h1, l1);
        split_bf16(v.z, h2, l2); split_bf16(v.w, h3, l3);
        uint2 ph, pl;
        ph.x = ((uint32_t)__bfloat16_as_ushort(h1) << 16) | __bfloat16_as_ushort(h0);
        ph.y = ((uint32_t)__bfloat16_as_ushort(h3) << 16) | __bfloat16_as_ushort(h2);
        pl.x = ((uint32_t)__bfloat16_as_ushort(l1) << 16) | __bfloat16_as_ushort(l0);
        pl.y = ((uint32_t)__bfloat16_as_ushort(l3) << 16) | __bfloat16_as_ushort(l2);
        reinterpret_cast<uint2*>(g_xh)[idx] = ph;
        reinterpret_cast<uint2*>(g_xl)[idx] = pl;
    }
}

__global__ void pack_w_kernel(const float* __restrict__ qkv_w, const float* __restrict__ qkv_b,
                              const float* __restrict__ off_w, const float* __restrict__ off_b,
                              const float* __restrict__ attw_w, const float* __restrict__ attw_b,
                              const float* __restrict__ proj_w)
{
    int idx = blockIdx.x * blockDim.x + threadIdx.x;
    if (idx < DD * NCAT) {
        int k = idx / NCAT, n = idx % NCAT;
        float w;
        if (n < 256)      w = qkv_w[k * 768 + 512 + n];
        else if (n < 320) w = off_w[k * 64 + (n - 256)];
        else if (n < 352) w = attw_w[k * 32 + (n - 320)];
        else              w = 0.0f;
        __nv_bfloat16 h, l; split_bf16(w, h, l);
        g_w1h[idx] = h; g_w1l[idx] = l;
    }
    int idx2 = idx - DD * NCAT;
    if (idx2 >= 0 && idx2 < DD * DD) {
        __nv_bfloat16 h, l; split_bf16(proj_w[idx2], h, l);
        g_w2h[idx2] = h; g_w2l[idx2] = l;
    }
    if (idx < NCAT) {
        float bv;
        if (idx < 256)      bv = qkv_b[512 + idx];
        else if (idx < 320) bv = off_b[idx - 256];
        else if (idx < 352) bv = attw_b[idx - 320];
        else                bv = 0.0f;
        g_bcat[idx] = bv;
    }
}

// =================== mma.sync bf16x3 GEMM (proven R10 config) ===============
#define A_ROW_B   80
#define B_ROW_B   144
#define SM_A_SZ   10240                     // 128*80
#define SM_B_OFF  20480                     // 2 * SM_A_SZ
#define SM_B_SZ   4608                      // 32*144
#define SM_STAGE  29696                     // 20480 + 2*4608
#define N_STAGE   3
#define SMEM_GEMM_SZ (N_STAGE * SM_STAGE)   // 89088

__device__ __forceinline__ void mma_gemm_body(const __nv_bfloat16* __restrict__ Ah,
                                              const __nv_bfloat16* __restrict__ Al,
                                              const __nv_bfloat16* __restrict__ Bh,
                                              const __nv_bfloat16* __restrict__ Bl,
                                              const float* __restrict__ bias,
                                              float* __restrict__ C, int Nw)
{
    extern __shared__ char smem[];
    const uint32_t sm = smem_to_u32(smem);
    const int tid = threadIdx.x;
    const int lane = tid & 31, wid = tid >> 5;
    const int warp_m = wid >> 1, warp_n = wid & 1;
    const int m0 = blockIdx.y * 128, n0 = blockIdx.x * 64;

    const __nv_bfloat16* a_src[4]; uint32_t a_dst[4];
#pragma unroll
    for (int i = 0; i < 4; ++i) {
        int c = tid + i * 256;
        int mat = c >> 9, cc = c & 511, row = cc >> 2, kc = cc & 3;
        a_src[i] = (mat ? Al : Ah) + (size_t)(m0 + row) * DD + kc * 8;
        a_dst[i] = sm + mat * SM_A_SZ + row * A_ROW_B + kc * 16;
    }
    const __nv_bfloat16* b_src[2]; uint32_t b_dst[2];
#pragma unroll
    for (int j = 0; j < 2; ++j) {
        int c = tid + j * 256;
        int mat = c >> 8, cc = c & 255, row = cc >> 3, nc = cc & 7;
        b_src[j] = (mat ? Bl : Bh) + (size_t)row * Nw + n0 + nc * 8;
        b_dst[j] = sm + SM_B_OFF + mat * SM_B_SZ + row * B_ROW_B + nc * 16;
    }

    float acc[2][4][4];
#pragma unroll
    for (int mt = 0; mt < 2; ++mt)
#pragma unroll
        for (int nt = 0; nt < 4; ++nt)
#pragma unroll
            for (int e = 0; e < 4; ++e) acc[mt][nt][e] = 0.0f;

    auto prefetch = [&](int s, int buf) {
        uint32_t bo = (uint32_t)buf * SM_STAGE;
#pragma unroll
        for (int i = 0; i < 4; ++i) cp_async16(a_dst[i] + bo, a_src[i] + s * 32);
#pragma unroll
        for (int j = 0; j < 2; ++j) cp_async16(b_dst[j] + bo, b_src[j] + (size_t)s * 32 * Nw);
        cp_commit();
    };

    prefetch(0, 0);
    prefetch(1, 1);
    int buf = 0;
    for (int s = 0; s < 8; ++s) {
        if (s < 7) asm volatile("cp.async.wait_group 1;");
        else       asm volatile("cp.async.wait_group 0;");
        __syncthreads();
        if (s + 2 < 8) prefetch(s + 2, (s + 2) % 3);

        uint32_t base = sm + (uint32_t)buf * SM_STAGE;
#pragma unroll
        for (int k16 = 0; k16 < 2; ++k16) {
            const int kk = k16 * 16;
            uint32_t ah[2][4], al[2][4];
            const int rA = lane & 15, cA = kk + ((lane >> 4) << 3);
#pragma unroll
            for (int mt = 0; mt < 2; ++mt) {
                uint32_t ad = base + (warp_m * 32 + mt * 16 + rA) * A_ROW_B + cA * 2;
                ldsm_x4(ah[mt], ad);
                ldsm_x4(al[mt], ad + SM_A_SZ);
            }
            uint32_t bh[4][2], bl[4][2];
            const int rB = kk + (lane & 15);
            const int cB = warp_n * 32 + ((lane >> 4) << 3);
#pragma unroll
            for (int ntp = 0; ntp < 2; ++ntp) {
                uint32_t bd = base + SM_B_OFF + rB * B_ROW_B + (cB + ntp * 16) * 2;
                uint32_t t4[4];
                ldsm_x4t(t4, bd);
                bh[2 * ntp][0] = t4[0]; bh[2 * ntp][1] = t4[1];
                bh[2 * ntp + 1][0] = t4[2]; bh[2 * ntp + 1][1] = t4[3];
                ldsm_x4t(t4, bd + SM_B_SZ);
                bl[2 * ntp][0] = t4[0]; bl[2 * ntp][1] = t4[1];
                bl[2 * ntp + 1][0] = t4[2]; bl[2 * ntp + 1][1] = t4[3];
            }
#pragma unroll
            for (int mt = 0; mt < 2; ++mt)
#pragma unroll
                for (int nt = 0; nt < 4; ++nt)
                    mma_bf16(acc[mt][nt], ah[mt], bh[nt]);
#pragma unroll
            for (int mt = 0; mt < 2; ++mt)
#pragma unroll
                for (int nt = 0; nt < 4; ++nt)
                    mma_bf16(acc[mt][nt], al[mt], bh[nt]);
#pragma unroll
            for (int mt = 0; mt < 2; ++mt)
#pragma unroll
                for (int nt = 0; nt < 4; ++nt)
                    mma_bf16(acc[mt][nt], ah[mt], bl[nt]);
        }
        buf = (buf + 1) % 3;
    }

    const int rbase = m0 + warp_m * 32 + (lane >> 2);
    const int cbase = n0 + warp_n * 32 + (lane & 3) * 2;
#pragma unroll
    for (int mt = 0; mt < 2; ++mt) {
#pragma unroll
        for (int nt = 0; nt < 4; ++nt) {
            int col = cbase + nt * 8;
            float b0 = bias[col], b1 = bias[col + 1];
            float2 v0 = make_float2(acc[mt][nt][0] + b0, acc[mt][nt][1] + b1);
            float2 v1 = make_float2(acc[mt][nt][2] + b0, acc[mt][nt][3] + b1);
            *reinterpret_cast<float2*>(C + (size_t)(rbase + mt * 16) * Nw + col) = v0;
            *reinterpret_cast<float2*>(C + (size_t)(rbase + mt * 16 + 8) * Nw + col) = v1;
        }
    }
}

__global__ __launch_bounds__(256, 2) void gemm1_kernel()
{
    mma_gemm_body(g_xh, g_xl, g_w1h, g_w1l, g_bcat, g_y, NCAT);
}

__global__ __launch_bounds__(256, 2) void gemm2_kernel(const float* __restrict__ proj_b,
                                                       float* __restrict__ out)
{
    mma_gemm_body(g_midh, g_midl, g_w2h, g_w2l, proj_b, out, DD);
}

// ---------------- deformable sampling: async window + fused prep ------------
// One block per (b, h, 16x16 tile). Window rows are 128B-contiguous in g_y, so
// the 20x20x32 window is loaded via cp.async (8x16B chunks per position,
// zero-filled OOB via src-size=0 — matches reference's zero-weight path).
// Copies are issued FIRST and fly while the lane-parallel prep (tanh/softmax/
// bilinear decomposition) computes; then one wait + barrier, then the R12
// gather loop (serial FFMA form — proven fastest).
#define PREP_STRIDE 24                       // floats per pixel (16B aligned)
#define SMEM_WIN_SZ (WIN * WIN * HD * 4)     // 51200
#define SMEM_SAMP_SZ (SMEM_WIN_SZ + 256 * PREP_STRIDE * 4)   // 75776

__global__ __launch_bounds__(256) void sample_kernel()
{
    extern __shared__ float vt[];            // window [400][32], then prep [256][24]
    float* prep = vt + WIN * WIN * HD;
    const int tid = threadIdx.x;
    const int lane = tid & 31, wid = tid >> 5;

    const int t = blockIdx.x;
    const int tile = t & 15;
    const int h = (t >> 4) & 7;
    const int b = t >> 7;
    const int tx0 = (tile & 3) * TILE_PX;
    const int ty0 = (tile >> 2) * TILE_PX;

    const uint32_t vt_sm = smem_to_u32(vt);

    // ---- issue async window load: 400 positions x 128B, 8 chunks each ----
    {
        const float* ybase = g_y + (size_t)b * NN * NCAT + h * HD;
        // 3200 chunks of 16B; thread tid handles chunks tid, tid+256, ...
#pragma unroll
        for (int it = 0; it < 13; ++it) {
            int c = tid + it * 256;
            if (it == 12 && c >= 3200) break;
            int pos = c >> 3, sub = c & 7;
            int py = pos / WIN, px = pos % WIN;
            int gy = ty0 - 2 + py, gx = tx0 - 2 + px;
            bool valid = (gy >= 0 && gy < 64 && gx >= 0 && gx < 64);
            int gyc = valid ? gy : 0, gxc = valid ? gx : 0;   // clamp (unread if sz=0)
            const float* src = ybase + (size_t)(gyc * 64 + gxc) * NCAT + sub * 4;
            cp_async16_z(vt_sm + (uint32_t)(pos * HD + sub * 4) * 4, src, valid ? 16 : 0);
        }
        cp_commit();
    }

    // ---- lane-parallel prep while window copies fly: pixel q = wid*32+lane --
    {
        int q = wid * 32 + lane;
        int py = q >> 4, px = q & 15;
        int n = (ty0 + py) * 64 + (tx0 + px);
        const float* yrow = g_y + (size_t)(b * NN + n) * NCAT;

        float4 o0 = *reinterpret_cast<const float4*>(yrow + 256 + h * 8);
        float4 o1 = *reinterpret_cast<const float4*>(yrow + 256 + h * 8 + 4);
        float4 av = *reinterpret_cast<const float4*>(yrow + 320 + h * 4);
        float offr[8] = {o0.x, o0.y, o0.z, o0.w, o1.x, o1.y, o1.z, o1.w};
        float aw[4] = {av.x, av.y, av.z, av.w};

        float mx = fmaxf(fmaxf(aw[0], aw[1]), fmaxf(aw[2], aw[3]));
        float s = 0.0f;
#pragma unroll
        for (int p = 0; p < NP; ++p) { aw[p] = __expf(aw[p] - mx); s += aw[p]; }
        float inv = 1.0f / s;

        float pxl = (float)px + 2.0f;
        float pyl = (float)py + 2.0f;

        int offs[4]; float4 w[4];
#pragma unroll
        for (int p = 0; p < NP; ++p) {
            float lgx = pxl + 2.0f * tanhf(offr[2 * p]);
            float lgy = pyl + 2.0f * tanhf(offr[2 * p + 1]);
            float x0f = floorf(lgx), y0f = floorf(lgy);
            float wx1 = lgx - x0f, wy1 = lgy - y0f;
            float wx0 = 1.0f - wx1, wy0 = 1.0f - wy1;
            float ap = aw[p] * inv;
            w[p].x = ap * wx0 * wy0;
            w[p].y = ap * wx1 * wy0;
            w[p].z = ap * wx0 * wy1;
            w[p].w = ap * wx1 * wy1;
            offs[p] = ((int)y0f * WIN + (int)x0f) * HD;
        }
        float* dst = prep + q * PREP_STRIDE;
        *reinterpret_cast<int4*>(dst) = make_int4(offs[0], offs[1], offs[2], offs[3]);
        *reinterpret_cast<float4*>(dst + 4)  = w[0];
        *reinterpret_cast<float4*>(dst + 8)  = w[1];
        *reinterpret_cast<float4*>(dst + 12) = w[2];
        *reinterpret_cast<float4*>(dst + 16) = w[3];
    }

    asm volatile("cp.async.wait_group 0;");
    __syncthreads();

    const float* basep = vt + lane;

    // ---- main loop: warp w handles pixels [32w, 32w+32) (R12-proven form) --
#pragma unroll 4
    for (int j = 0; j < 32; ++j) {
        int q = wid * 32 + j;
        const float* pp = prep + q * PREP_STRIDE;
        int4 off  = *reinterpret_cast<const int4*>(pp);
        float4 w0 = *reinterpret_cast<const float4*>(pp + 4);
        float4 w1 = *reinterpret_cast<const float4*>(pp + 8);
        float4 w2 = *reinterpret_cast<const float4*>(pp + 12);
        float4 w3 = *reinterpret_cast<const float4*>(pp + 16);

        const float* c0 = basep + off.x;
        const float* c1 = basep + off.y;
        const float* c2 = basep + off.z;
        const float* c3 = basep + off.w;
        float acc;
        acc  = w0.x * c0[0] + w0.y * c0[HD] + w0.z * c0[WIN * HD] + w0.w * c0[WIN * HD + HD];
        acc += w1.x * c1[0] + w1.y * c1[HD] + w1.z * c1[WIN * HD] + w1.w * c1[WIN * HD + HD];
        acc += w2.x * c2[0] + w2.y * c2[HD] + w2.z * c2[WIN * HD] + w2.w * c2[WIN * HD + HD];
        acc += w3.x * c3[0] + w3.y * c3[HD] + w3.z * c3[WIN * HD] + w3.w * c3[WIN * HD + HD];

        int n = (ty0 + (q >> 4)) * 64 + (tx0 + (q & 15));
        size_t ofs = (size_t)(b * NN + n) * DD + h * HD + lane;
        __nv_bfloat16 hh, ll; split_bf16(acc, hh, ll);
        g_midh[ofs] = hh;
        g_midl[ofs] = ll;
    }
}

// ---------------- launch ----------------
extern "C" void kernel_launch(void* const* d_in, const int* in_sizes, int n_in,
                              void* d_out, int out_size)
{
    const float* x      = (const float*)d_in[0];
    const float* qkv_w  = (const float*)d_in[1];
    const float* qkv_b  = (const float*)d_in[2];
    const float* off_w  = (const float*)d_in[3];
    const float* off_b  = (const float*)d_in[4];
    const float* attw_w = (const float*)d_in[5];
    const float* attw_b = (const float*)d_in[6];
    const float* proj_w = (const float*)d_in[7];
    const float* proj_b = (const float*)d_in[8];
    float* out = (float*)d_out;

    cudaFuncSetAttribute(gemm1_kernel, cudaFuncAttributeMaxDynamicSharedMemorySize, SMEM_GEMM_SZ);
    cudaFuncSetAttribute(gemm2_kernel, cudaFuncAttributeMaxDynamicSharedMemorySize, SMEM_GEMM_SZ);
    cudaFuncSetAttribute(sample_kernel, cudaFuncAttributeMaxDynamicSharedMemorySize, SMEM_SAMP_SZ);

    // 1) split inputs/weights into bf16 hi/lo
    pack_x_kernel<<<(MM * DD / 4 + 255) / 256, 256>>>(x);
    pack_w_kernel<<<(DD * NCAT + DD * DD + 255) / 256, 256>>>(
        qkv_w, qkv_b, off_w, off_b, attw_w, attw_b, proj_w);

    // 2) stage-1 GEMM (mma.sync bf16x3): X[32768,256] @ Wcat[256,384] -> g_y
    gemm1_kernel<<<dim3(NCAT / 64, MM / 128), 256, SMEM_GEMM_SZ>>>();

    // 3) deformable sampling: async window load + fused in-smem prep
    sample_kernel<<<BB * NH * 16, 256, SMEM_SAMP_SZ>>>();

    // 4) output projection (mma.sync bf16x3): mid @ proj_w[256,256] + b -> out
    gemm2_kernel<<<dim3(DD / 64, MM / 128), 256, SMEM_GEMM_SZ>>>(proj_b, out);
}

// round 15
// speedup vs baseline: 1.2715x; 1.1523x over previous
#include <cuda_runtime.h>
#include <cuda_bf16.h>
#include <cuda_fp16.h>
#include <cstdint>
#include <math.h>

// Problem constants (fixed shapes from setup_inputs)
#define BB   8
#define NN   4096      // 64*64
#define DD   256
#define NH   8
#define NP   4
#define HD   32
#define MM   (BB*NN)   // 32768 rows
#define NCAT 384       // 256 (v) + 64 (off) + 32 (attw) + 32 pad

#define TILE_PX  16
#define WIN      20                         // 16 + 2*2 halo

// ---------------- scratch (device globals; no allocations allowed) ----------
__device__ float g_y[(size_t)MM * NCAT];          // stage-1 output: v | off | attw
__device__ float g_bcat[NCAT];                    // packed stage-1 bias
__device__ __half g_xh[(size_t)MM * DD];          // x as fp16 (single image)
__device__ __nv_bfloat16 g_midh[(size_t)MM * DD]; // sampled output split hi (bf16)
__device__ __nv_bfloat16 g_midl[(size_t)MM * DD]; // sampled output split lo (bf16)
__device__ __half g_w1h[DD * NCAT];               // [k][n] stage-1 weights fp16 hi
__device__ __half g_w1l[DD * NCAT];               // [k][n] stage-1 weights fp16 lo
__device__ __nv_bfloat16 g_w2h[DD * DD];          // [k][n] proj weights bf16 hi
__device__ __nv_bfloat16 g_w2l[DD * DD];

// =================== helpers ===================
__device__ __forceinline__ uint32_t smem_to_u32(const void* p) {
    uint32_t a;
    asm("{ .reg .u64 t; cvta.to.shared.u64 t, %1; cvt.u32.u64 %0, t; }" : "=r"(a) : "l"(p));
    return a;
}
__device__ __forceinline__ void split_bf16(float w, __nv_bfloat16& h, __nv_bfloat16& l) {
    h = __float2bfloat16_rn(w);
    l = __float2bfloat16_rn(w - __bfloat162float(h));
}
__device__ __forceinline__ void split_f16(float w, __half& h, __half& l) {
    h = __float2half_rn(w);
    l = __float2half_rn(w - __half2float(h));
}
__device__ __forceinline__ void cp_async16(uint32_t dst, const void* src) {
    asm volatile("{ .reg .u64 g; cvta.to.global.u64 g, %1; cp.async.cg.shared.global [%0], [g], 16; }"
                 :: "r"(dst), "l"(src));
}
// cp.async with dynamic src-size: bytes beyond sz are ZERO-FILLED (sz=0 -> all zeros)
__device__ __forceinline__ void cp_async16_z(uint32_t dst, const void* src, int sz) {
    asm volatile("{ .reg .u64 g; cvta.to.global.u64 g, %1; cp.async.cg.shared.global [%0], [g], 16, %2; }"
                 :: "r"(dst), "l"(src), "r"(sz));
}
__device__ __forceinline__ void cp_commit() {
    asm volatile("cp.async.commit_group;");
}
__device__ __forceinline__ void ldsm_x4(uint32_t (&r)[4], uint32_t addr) {
    asm volatile("ldmatrix.sync.aligned.m8n8.x4.shared.b16 {%0,%1,%2,%3}, [%4];"
                 : "=r"(r[0]), "=r"(r[1]), "=r"(r[2]), "=r"(r[3]) : "r"(addr));
}
__device__ __forceinline__ void ldsm_x4t(uint32_t (&r)[4], uint32_t addr) {
    asm volatile("ldmatrix.sync.aligned.m8n8.x4.trans.shared.b16 {%0,%1,%2,%3}, [%4];"
                 : "=r"(r[0]), "=r"(r[1]), "=r"(r[2]), "=r"(r[3]) : "r"(addr));
}
__device__ __forceinline__ void mma_bf16(float (&c)[4], const uint32_t (&a)[4], const uint32_t (&b)[2]) {
    asm volatile("mma.sync.aligned.m16n8k16.row.col.f32.bf16.bf16.f32 "
                 "{%0,%1,%2,%3}, {%4,%5,%6,%7}, {%8,%9}, {%0,%1,%2,%3};"
                 : "+f"(c[0]), "+f"(c[1]), "+f"(c[2]), "+f"(c[3])
                 : "r"(a[0]), "r"(a[1]), "r"(a[2]), "r"(a[3]), "r"(b[0]), "r"(b[1]));
}
__device__ __forceinline__ void mma_f16(float (&c)[4], const uint32_t (&a)[4], const uint32_t (&b)[2]) {
    asm volatile("mma.sync.aligned.m16n8k16.row.col.f32.f16.f16.f32 "
                 "{%0,%1,%2,%3}, {%4,%5,%6,%7}, {%8,%9}, {%0,%1,%2,%3};"
                 : "+f"(c[0]), "+f"(c[1]), "+f"(c[2]), "+f"(c[3])
                 : "r"(a[0]), "r"(a[1]), "r"(a[2]), "r"(a[3]), "r"(b[0]), "r"(b[1]));
}

// =================== pack kernels ===================
// x -> single fp16 image (fp16 keeps 11 mantissa bits; residual handled by W split)
__global__ void pack_x_kernel(const float* __restrict__ x)
{
    int idx = blockIdx.x * blockDim.x + threadIdx.x;   // over MM*DD/4
    if (idx < MM * DD / 4) {
        float4 v = reinterpret_cast<const float4*>(x)[idx];
        __half2 p0 = make_half2(__float2half_rn(v.x), __float2half_rn(v.y));
        __half2 p1 = make_half2(__float2half_rn(v.z), __float2half_rn(v.w));
        uint2 pk;
        pk.x = *reinterpret_cast<uint32_t*>(&p0);
        pk.y = *reinterpret_cast<uint32_t*>(&p1);
        reinterpret_cast<uint2*>(g_xh)[idx] = pk;
    }
}

// fused: stage-1 weight concat/split (fp16) + bias + proj weight split (bf16)
__global__ void pack_w_kernel(const float* __restrict__ qkv_w, const float* __restrict__ qkv_b,
                              const float* __restrict__ off_w, const float* __restrict__ off_b,
                              const float* __restrict__ attw_w, const float* __restrict__ attw_b,
                              const float* __restrict__ proj_w)
{
    int idx = blockIdx.x * blockDim.x + threadIdx.x;
    if (idx < DD * NCAT) {
        int k = idx / NCAT, n = idx % NCAT;
        float w;
        if (n < 256)      w = qkv_w[k * 768 + 512 + n];
        else if (n < 320) w = off_w[k * 64 + (n - 256)];
        else if (n < 352) w = attw_w[k * 32 + (n - 320)];
        else              w = 0.0f;
        __half h, l; split_f16(w, h, l);
        g_w1h[idx] = h; g_w1l[idx] = l;
    }
    int idx2 = idx - DD * NCAT;
    if (idx2 >= 0 && idx2 < DD * DD) {
        __nv_bfloat16 h, l; split_bf16(proj_w[idx2], h, l);
        g_w2h[idx2] = h; g_w2l[idx2] = l;
    }
    if (idx < NCAT) {
        float bv;
        if (idx < 256)      bv = qkv_b[512 + idx];
        else if (idx < 320) bv = off_b[idx - 256];
        else if (idx < 352) bv = attw_b[idx - 320];
        else                bv = 0.0f;
        g_bcat[idx] = bv;
    }
}

// =================== GEMM common tile constants ===================
#define A_ROW_B   80
#define B_ROW_B   144
#define SM_A_SZ   10240                     // one image: 128*80
#define SM_B_SZ   4608                      // 32*144

// ---------- gemm1: fp16 2-term (A single image, B hi/lo) ----------
#define G1_B_OFF   SM_A_SZ                  // 10240
#define G1_STAGE   (SM_A_SZ + 2 * SM_B_SZ)  // 19456
#define G1_SMEM    (3 * G1_STAGE)           // 58368

__global__ __launch_bounds__(256, 2) void gemm1_kernel()
{
    extern __shared__ char smem[];
    const uint32_t sm = smem_to_u32(smem);
    const int tid = threadIdx.x;
    const int lane = tid & 31, wid = tid >> 5;
    const int warp_m = wid >> 1, warp_n = wid & 1;
    const int m0 = blockIdx.y * 128, n0 = blockIdx.x * 64;
    const int Nw = NCAT;

    // A: 512 chunks of 16B (single image), 2 per thread
    const __half* a_src[2]; uint32_t a_dst[2];
#pragma unroll
    for (int i = 0; i < 2; ++i) {
        int c = tid + i * 256;
        int row = c >> 2, kc = c & 3;
        a_src[i] = g_xh + (size_t)(m0 + row) * DD + kc * 8;
        a_dst[i] = sm + row * A_ROW_B + kc * 16;
    }
    // B: 512 chunks (2 images), 2 per thread
    const __half* b_src[2]; uint32_t b_dst[2];
#pragma unroll
    for (int j = 0; j < 2; ++j) {
        int c = tid + j * 256;
        int mat = c >> 8, cc = c & 255, row = cc >> 3, nc = cc & 7;
        b_src[j] = (mat ? g_w1l : g_w1h) + (size_t)row * Nw + n0 + nc * 8;
        b_dst[j] = sm + G1_B_OFF + mat * SM_B_SZ + row * B_ROW_B + nc * 16;
    }

    float acc[2][4][4];
#pragma unroll
    for (int mt = 0; mt < 2; ++mt)
#pragma unroll
        for (int nt = 0; nt < 4; ++nt)
#pragma unroll
            for (int e = 0; e < 4; ++e) acc[mt][nt][e] = 0.0f;

    auto prefetch = [&](int s, int buf) {
        uint32_t bo = (uint32_t)buf * G1_STAGE;
#pragma unroll
        for (int i = 0; i < 2; ++i) cp_async16(a_dst[i] + bo, a_src[i] + s * 32);
#pragma unroll
        for (int j = 0; j < 2; ++j) cp_async16(b_dst[j] + bo, b_src[j] + (size_t)s * 32 * Nw);
        cp_commit();
    };

    prefetch(0, 0);
    prefetch(1, 1);
    int buf = 0;
    for (int s = 0; s < 8; ++s) {
        if (s < 7) asm volatile("cp.async.wait_group 1;");
        else       asm volatile("cp.async.wait_group 0;");
        __syncthreads();
        if (s + 2 < 8) prefetch(s + 2, (s + 2) % 3);

        uint32_t base = sm + (uint32_t)buf * G1_STAGE;
#pragma unroll
        for (int k16 = 0; k16 < 2; ++k16) {
            const int kk = k16 * 16;
            uint32_t ah[2][4];
            const int rA = lane & 15, cA = kk + ((lane >> 4) << 3);
#pragma unroll
            for (int mt = 0; mt < 2; ++mt) {
                uint32_t ad = base + (warp_m * 32 + mt * 16 + rA) * A_ROW_B + cA * 2;
                ldsm_x4(ah[mt], ad);
            }
            uint32_t bh[4][2], bl[4][2];
            const int rB = kk + (lane & 15);
            const int cB = warp_n * 32 + ((lane >> 4) << 3);
#pragma unroll
            for (int ntp = 0; ntp < 2; ++ntp) {
                uint32_t bd = base + G1_B_OFF + rB * B_ROW_B + (cB + ntp * 16) * 2;
                uint32_t t4[4];
                ldsm_x4t(t4, bd);
                bh[2 * ntp][0] = t4[0]; bh[2 * ntp][1] = t4[1];
                bh[2 * ntp + 1][0] = t4[2]; bh[2 * ntp + 1][1] = t4[3];
                ldsm_x4t(t4, bd + SM_B_SZ);
                bl[2 * ntp][0] = t4[0]; bl[2 * ntp][1] = t4[1];
                bl[2 * ntp + 1][0] = t4[2]; bl[2 * ntp + 1][1] = t4[3];
            }
            // 2 terms: Ah*Bh then Ah*Bl (per-accumulator order preserved)
#pragma unroll
            for (int mt = 0; mt < 2; ++mt)
#pragma unroll
                for (int nt = 0; nt < 4; ++nt)
                    mma_f16(acc[mt][nt], ah[mt], bh[nt]);
#pragma unroll
            for (int mt = 0; mt < 2; ++mt)
#pragma unroll
                for (int nt = 0; nt < 4; ++nt)
                    mma_f16(acc[mt][nt], ah[mt], bl[nt]);
        }
        buf = (buf + 1) % 3;
    }

    const int rbase = m0 + warp_m * 32 + (lane >> 2);
    const int cbase = n0 + warp_n * 32 + (lane & 3) * 2;
#pragma unroll
    for (int mt = 0; mt < 2; ++mt) {
#pragma unroll
        for (int nt = 0; nt < 4; ++nt) {
            int col = cbase + nt * 8;
            float b0 = g_bcat[col], b1 = g_bcat[col + 1];
            float2 v0 = make_float2(acc[mt][nt][0] + b0, acc[mt][nt][1] + b1);
            float2 v1 = make_float2(acc[mt][nt][2] + b0, acc[mt][nt][3] + b1);
            *reinterpret_cast<float2*>(g_y + (size_t)(rbase + mt * 16) * Nw + col) = v0;
            *reinterpret_cast<float2*>(g_y + (size_t)(rbase + mt * 16 + 8) * Nw + col) = v1;
        }
    }
}

// ---------- gemm2: bf16 3-term (proven R10/R14 config) ----------
#define G2_B_OFF  20480                     // 2 * SM_A_SZ
#define G2_STAGE  29696                     // 20480 + 2*4608
#define G2_SMEM   (3 * G2_STAGE)            // 89088

__global__ __launch_bounds__(256, 2) void gemm2_kernel(const float* __restrict__ proj_b,
                                                       float* __restrict__ out)
{
    extern __shared__ char smem[];
    const uint32_t sm = smem_to_u32(smem);
    const int tid = threadIdx.x;
    const int lane = tid & 31, wid = tid >> 5;
    const int warp_m = wid >> 1, warp_n = wid & 1;
    const int m0 = blockIdx.y * 128, n0 = blockIdx.x * 64;
    const int Nw = DD;

    const __nv_bfloat16* a_src[4]; uint32_t a_dst[4];
#pragma unroll
    for (int i = 0; i < 4; ++i) {
        int c = tid + i * 256;
        int mat = c >> 9, cc = c & 511, row = cc >> 2, kc = cc & 3;
        a_src[i] = (mat ? g_midl : g_midh) + (size_t)(m0 + row) * DD + kc * 8;
        a_dst[i] = sm + mat * SM_A_SZ + row * A_ROW_B + kc * 16;
    }
    const __nv_bfloat16* b_src[2]; uint32_t b_dst[2];
#pragma unroll
    for (int j = 0; j < 2; ++j) {
        int c = tid + j * 256;
        int mat = c >> 8, cc = c & 255, row = cc >> 3, nc = cc & 7;
        b_src[j] = (mat ? g_w2l : g_w2h) + (size_t)row * Nw + n0 + nc * 8;
        b_dst[j] = sm + G2_B_OFF + mat * SM_B_SZ + row * B_ROW_B + nc * 16;
    }

    float acc[2][4][4];
#pragma unroll
    for (int mt = 0; mt < 2; ++mt)
#pragma unroll
        for (int nt = 0; nt < 4; ++nt)
#pragma unroll
            for (int e = 0; e < 4; ++e) acc[mt][nt][e] = 0.0f;

    auto prefetch = [&](int s, int buf) {
        uint32_t bo = (uint32_t)buf * G2_STAGE;
#pragma unroll
        for (int i = 0; i < 4; ++i) cp_async16(a_dst[i] + bo, a_src[i] + s * 32);
#pragma unroll
        for (int j = 0; j < 2; ++j) cp_async16(b_dst[j] + bo, b_src[j] + (size_t)s * 32 * Nw);
        cp_commit();
    };

    prefetch(0, 0);
    prefetch(1, 1);
    int buf = 0;
    for (int s = 0; s < 8; ++s) {
        if (s < 7) asm volatile("cp.async.wait_group 1;");
        else       asm volatile("cp.async.wait_group 0;");
        __syncthreads();
        if (s + 2 < 8) prefetch(s + 2, (s + 2) % 3);

        uint32_t base = sm + (uint32_t)buf * G2_STAGE;
#pragma unroll
        for (int k16 = 0; k16 < 2; ++k16) {
            const int kk = k16 * 16;
            uint32_t ah[2][4], al[2][4];
            const int rA = lane & 15, cA = kk + ((lane >> 4) << 3);
#pragma unroll
            for (int mt = 0; mt < 2; ++mt) {
                uint32_t ad = base + (warp_m * 32 + mt * 16 + rA) * A_ROW_B + cA * 2;
                ldsm_x4(ah[mt], ad);
                ldsm_x4(al[mt], ad + SM_A_SZ);
            }
            uint32_t bh[4][2], bl[4][2];
            const int rB = kk + (lane & 15);
            const int cB = warp_n * 32 + ((lane >> 4) << 3);
#pragma unroll
            for (int ntp = 0; ntp < 2; ++ntp) {
                uint32_t bd = base + G2_B_OFF + rB * B_ROW_B + (cB + ntp * 16) * 2;
                uint32_t t4[4];
                ldsm_x4t(t4, bd);
                bh[2 * ntp][0] = t4[0]; bh[2 * ntp][1] = t4[1];
                bh[2 * ntp + 1][0] = t4[2]; bh[2 * ntp + 1][1] = t4[3];
                ldsm_x4t(t4, bd + SM_B_SZ);
                bl[2 * ntp][0] = t4[0]; bl[2 * ntp][1] = t4[1];
                bl[2 * ntp + 1][0] = t4[2]; bl[2 * ntp + 1][1] = t4[3];
            }
#pragma unroll
            for (int mt = 0; mt < 2; ++mt)
#pragma unroll
                for (int nt = 0; nt < 4; ++nt)
                    mma_bf16(acc[mt][nt], ah[mt], bh[nt]);
#pragma unroll
            for (int mt = 0; mt < 2; ++mt)
#pragma unroll
                for (int nt = 0; nt < 4; ++nt)
                    mma_bf16(acc[mt][nt], al[mt], bh[nt]);
#pragma unroll
            for (int mt = 0; mt < 2; ++mt)
#pragma unroll
                for (int nt = 0; nt < 4; ++nt)
                    mma_bf16(acc[mt][nt], ah[mt], bl[nt]);
        }
        buf = (buf + 1) % 3;
    }

    const int rbase = m0 + warp_m * 32 + (lane >> 2);
    const int cbase = n0 + warp_n * 32 + (lane & 3) * 2;
#pragma unroll
    for (int mt = 0; mt < 2; ++mt) {
#pragma unroll
        for (int nt = 0; nt < 4; ++nt) {
            int col = cbase + nt * 8;
            float b0 = proj_b[col], b1 = proj_b[col + 1];
            float2 v0 = make_float2(acc[mt][nt][0] + b0, acc[mt][nt][1] + b1);
            float2 v1 = make_float2(acc[mt][nt][2] + b0, acc[mt][nt][3] + b1);
            *reinterpret_cast<float2*>(out + (size_t)(rbase + mt * 16) * Nw + col) = v0;
            *reinterpret_cast<float2*>(out + (size_t)(rbase + mt * 16 + 8) * Nw + col) = v1;
        }
    }
}

// ---------------- deformable sampling: async window + fused prep (R14) ------
#define PREP_STRIDE 24                       // floats per pixel (16B aligned)
#define SMEM_WIN_SZ (WIN * WIN * HD * 4)     // 51200
#define SMEM_SAMP_SZ (SMEM_WIN_SZ + 256 * PREP_STRIDE * 4)   // 75776

__global__ __launch_bounds__(256) void sample_kernel()
{
    extern __shared__ float vt[];            // window [400][32], then prep [256][24]
    float* prep = vt + WIN * WIN * HD;
    const int tid = threadIdx.x;
    const int lane = tid & 31, wid = tid >> 5;

    const int t = blockIdx.x;
    const int tile = t & 15;
    const int h = (t >> 4) & 7;
    const int b = t >> 7;
    const int tx0 = (tile & 3) * TILE_PX;
    const int ty0 = (tile >> 2) * TILE_PX;

    const uint32_t vt_sm = smem_to_u32(vt);

    // ---- issue async window load: 400 positions x 128B, 8 chunks each ----
    {
        const float* ybase = g_y + (size_t)b * NN * NCAT + h * HD;
#pragma unroll
        for (int it = 0; it < 13; ++it) {
            int c = tid + it * 256;
            if (it == 12 && c >= 3200) break;
            int pos = c >> 3, sub = c & 7;
            int py = pos / WIN, px = pos % WIN;
            int gy = ty0 - 2 + py, gx = tx0 - 2 + px;
            bool valid = (gy >= 0 && gy < 64 && gx >= 0 && gx < 64);
            int gyc = valid ? gy : 0, gxc = valid ? gx : 0;   // clamp (unread if sz=0)
            const float* src = ybase + (size_t)(gyc * 64 + gxc) * NCAT + sub * 4;
            cp_async16_z(vt_sm + (uint32_t)(pos * HD + sub * 4) * 4, src, valid ? 16 : 0);
        }
        cp_commit();
    }

    // ---- lane-parallel prep while window copies fly ----
    {
        int q = wid * 32 + lane;
        int py = q >> 4, px = q & 15;
        int n = (ty0 + py) * 64 + (tx0 + px);
        const float* yrow = g_y + (size_t)(b * NN + n) * NCAT;

        float4 o0 = *reinterpret_cast<const float4*>(yrow + 256 + h * 8);
        float4 o1 = *reinterpret_cast<const float4*>(yrow + 256 + h * 8 + 4);
        float4 av = *reinterpret_cast<const float4*>(yrow + 320 + h * 4);
        float offr[8] = {o0.x, o0.y, o0.z, o0.w, o1.x, o1.y, o1.z, o1.w};
        float aw[4] = {av.x, av.y, av.z, av.w};

        float mx = fmaxf(fmaxf(aw[0], aw[1]), fmaxf(aw[2], aw[3]));
        float s = 0.0f;
#pragma unroll
        for (int p = 0; p < NP; ++p) { aw[p] = __expf(aw[p] - mx); s += aw[p]; }
        float inv = 1.0f / s;

        float pxl = (float)px + 2.0f;
        float pyl = (float)py + 2.0f;

        int offs[4]; float4 w[4];
#pragma unroll
        for (int p = 0; p < NP; ++p) {
            float lgx = pxl + 2.0f * tanhf(offr[2 * p]);
            float lgy = pyl + 2.0f * tanhf(offr[2 * p + 1]);
            float x0f = floorf(lgx), y0f = floorf(lgy);
            float wx1 = lgx - x0f, wy1 = lgy - y0f;
            float wx0 = 1.0f - wx1, wy0 = 1.0f - wy1;
            float ap = aw[p] * inv;
            w[p].x = ap * wx0 * wy0;
            w[p].y = ap * wx1 * wy0;
            w[p].z = ap * wx0 * wy1;
            w[p].w = ap * wx1 * wy1;
            offs[p] = ((int)y0f * WIN + (int)x0f) * HD;
        }
        float* dst = prep + q * PREP_STRIDE;
        *reinterpret_cast<int4*>(dst) = make_int4(offs[0], offs[1], offs[2], offs[3]);
        *reinterpret_cast<float4*>(dst + 4)  = w[0];
        *reinterpret_cast<float4*>(dst + 8)  = w[1];
        *reinterpret_cast<float4*>(dst + 12) = w[2];
        *reinterpret_cast<float4*>(dst + 16) = w[3];
    }

    asm volatile("cp.async.wait_group 0;");
    __syncthreads();

    const float* basep = vt + lane;

    // ---- main loop: warp w handles pixels [32w, 32w+32) ----
#pragma unroll 4
    for (int j = 0; j < 32; ++j) {
        int q = wid * 32 + j;
        const float* pp = prep + q * PREP_STRIDE;
        int4 off  = *reinterpret_cast<const int4*>(pp);
        float4 w0 = *reinterpret_cast<const float4*>(pp + 4);
        float4 w1 = *reinterpret_cast<const float4*>(pp + 8);
        float4 w2 = *reinterpret_cast<const float4*>(pp + 12);
        float4 w3 = *reinterpret_cast<const float4*>(pp + 16);

        const float* c0 = basep + off.x;
        const float* c1 = basep + off.y;
        const float* c2 = basep + off.z;
        const float* c3 = basep + off.w;
        float acc;
        acc  = w0.x * c0[0] + w0.y * c0[HD] + w0.z * c0[WIN * HD] + w0.w * c0[WIN * HD + HD];
        acc += w1.x * c1[0] + w1.y * c1[HD] + w1.z * c1[WIN * HD] + w1.w * c1[WIN * HD + HD];
        acc += w2.x * c2[0] + w2.y * c2[HD] + w2.z * c2[WIN * HD] + w2.w * c2[WIN * HD + HD];
        acc += w3.x * c3[0] + w3.y * c3[HD] + w3.z * c3[WIN * HD] + w3.w * c3[WIN * HD + HD];

        int n = (ty0 + (q >> 4)) * 64 + (tx0 + (q & 15));
        size_t ofs = (size_t)(b * NN + n) * DD + h * HD + lane;
        __nv_bfloat16 hh, ll; split_bf16(acc, hh, ll);
        g_midh[ofs] = hh;
        g_midl[ofs] = ll;
    }
}

// ---------------- launch ----------------
extern "C" void kernel_launch(void* const* d_in, const int* in_sizes, int n_in,
                              void* d_out, int out_size)
{
    const float* x      = (const float*)d_in[0];
    const float* qkv_w  = (const float*)d_in[1];
    const float* qkv_b  = (const float*)d_in[2];
    const float* off_w  = (const float*)d_in[3];
    const float* off_b  = (const float*)d_in[4];
    const float* attw_w = (const float*)d_in[5];
    const float* attw_b = (const float*)d_in[6];
    const float* proj_w = (const float*)d_in[7];
    const float* proj_b = (const float*)d_in[8];
    float* out = (float*)d_out;

    cudaFuncSetAttribute(gemm1_kernel, cudaFuncAttributeMaxDynamicSharedMemorySize, G1_SMEM);
    cudaFuncSetAttribute(gemm2_kernel, cudaFuncAttributeMaxDynamicSharedMemorySize, G2_SMEM);
    cudaFuncSetAttribute(sample_kernel, cudaFuncAttributeMaxDynamicSharedMemorySize, SMEM_SAMP_SZ);

    // 1) pack: x -> fp16 single image, w1 -> fp16 hi/lo, w2 -> bf16 hi/lo
    pack_x_kernel<<<(MM * DD / 4 + 255) / 256, 256>>>(x);
    pack_w_kernel<<<(DD * NCAT + DD * DD + 255) / 256, 256>>>(
        qkv_w, qkv_b, off_w, off_b, attw_w, attw_b, proj_w);

    // 2) stage-1 GEMM (fp16 2-term): X[32768,256] @ Wcat[256,384] -> g_y
    gemm1_kernel<<<dim3(NCAT / 64, MM / 128), 256, G1_SMEM>>>();

    // 3) deformable sampling (R14-proven)
    sample_kernel<<<BB * NH * 16, 256, SMEM_SAMP_SZ>>>();

    // 4) output projection (bf16 3-term): mid @ proj_w[256,256] + b -> out
    gemm2_kernel<<<dim3(DD / 64, MM / 128), 256, G2_SMEM>>>(proj_b, out);
}

// round 16
// speedup vs baseline: 1.3793x; 1.0848x over previous
#include <cuda_runtime.h>
#include <cuda_bf16.h>
#include <cuda_fp16.h>
#include <cstdint>
#include <math.h>

// Problem constants (fixed shapes from setup_inputs)
#define BB   8
#define NN   4096      // 64*64
#define DD   256
#define NH   8
#define NP   4
#define HD   32
#define MM   (BB*NN)   // 32768 rows
#define NCAT 384       // 256 (v) + 64 (off) + 32 (attw) + 32 pad

#define TILE_PX  16
#define WIN      20                         // 16 + 2*2 halo

// ---------------- scratch (device globals; no allocations allowed) ----------
__device__ float g_y[(size_t)MM * NCAT];          // stage-1 output: v | off | attw
__device__ float g_bcat[NCAT];                    // packed stage-1 bias
__device__ __half g_xh[(size_t)MM * DD];          // x as fp16 (single image)
__device__ __half g_mid[(size_t)MM * DD];         // sampled output as fp16 (single image)
__device__ __half g_w1h[DD * NCAT];               // [k][n] stage-1 weights fp16 hi
__device__ __half g_w1l[DD * NCAT];               // [k][n] stage-1 weights fp16 lo
__device__ __half g_w2h[DD * DD];                 // [k][n] proj weights fp16 hi
__device__ __half g_w2l[DD * DD];                 // [k][n] proj weights fp16 lo

// =================== helpers ===================
__device__ __forceinline__ uint32_t smem_to_u32(const void* p) {
    uint32_t a;
    asm("{ .reg .u64 t; cvta.to.shared.u64 t, %1; cvt.u32.u64 %0, t; }" : "=r"(a) : "l"(p));
    return a;
}
__device__ __forceinline__ void split_f16(float w, __half& h, __half& l) {
    h = __float2half_rn(w);
    l = __float2half_rn(w - __half2float(h));
}
__device__ __forceinline__ void cp_async16(uint32_t dst, const void* src) {
    asm volatile("{ .reg .u64 g; cvta.to.global.u64 g, %1; cp.async.cg.shared.global [%0], [g], 16; }"
                 :: "r"(dst), "l"(src));
}
// cp.async with dynamic src-size: bytes beyond sz are ZERO-FILLED (sz=0 -> all zeros)
__device__ __forceinline__ void cp_async16_z(uint32_t dst, const void* src, int sz) {
    asm volatile("{ .reg .u64 g; cvta.to.global.u64 g, %1; cp.async.cg.shared.global [%0], [g], 16, %2; }"
                 :: "r"(dst), "l"(src), "r"(sz));
}
__device__ __forceinline__ void cp_commit() {
    asm volatile("cp.async.commit_group;");
}
__device__ __forceinline__ void ldsm_x4(uint32_t (&r)[4], uint32_t addr) {
    asm volatile("ldmatrix.sync.aligned.m8n8.x4.shared.b16 {%0,%1,%2,%3}, [%4];"
                 : "=r"(r[0]), "=r"(r[1]), "=r"(r[2]), "=r"(r[3]) : "r"(addr));
}
__device__ __forceinline__ void ldsm_x4t(uint32_t (&r)[4], uint32_t addr) {
    asm volatile("ldmatrix.sync.aligned.m8n8.x4.trans.shared.b16 {%0,%1,%2,%3}, [%4];"
                 : "=r"(r[0]), "=r"(r[1]), "=r"(r[2]), "=r"(r[3]) : "r"(addr));
}
__device__ __forceinline__ void mma_f16(float (&c)[4], const uint32_t (&a)[4], const uint32_t (&b)[2]) {
    asm volatile("mma.sync.aligned.m16n8k16.row.col.f32.f16.f16.f32 "
                 "{%0,%1,%2,%3}, {%4,%5,%6,%7}, {%8,%9}, {%0,%1,%2,%3};"
                 : "+f"(c[0]), "+f"(c[1]), "+f"(c[2]), "+f"(c[3])
                 : "r"(a[0]), "r"(a[1]), "r"(a[2]), "r"(a[3]), "r"(b[0]), "r"(b[1]));
}

// =================== pack kernels ===================
// x -> single fp16 image (fp16 keeps 11 mantissa bits; residual handled by W split)
__global__ void pack_x_kernel(const float* __restrict__ x)
{
    int idx = blockIdx.x * blockDim.x + threadIdx.x;   // over MM*DD/4
    if (idx < MM * DD / 4) {
        float4 v = reinterpret_cast<const float4*>(x)[idx];
        __half2 p0 = make_half2(__float2half_rn(v.x), __float2half_rn(v.y));
        __half2 p1 = make_half2(__float2half_rn(v.z), __float2half_rn(v.w));
        uint2 pk;
        pk.x = *reinterpret_cast<uint32_t*>(&p0);
        pk.y = *reinterpret_cast<uint32_t*>(&p1);
        reinterpret_cast<uint2*>(g_xh)[idx] = pk;
    }
}

// fused: stage-1 weight concat/split (fp16) + bias + proj weight split (fp16)
__global__ void pack_w_kernel(const float* __restrict__ qkv_w, const float* __restrict__ qkv_b,
                              const float* __restrict__ off_w, const float* __restrict__ off_b,
                              const float* __restrict__ attw_w, const float* __restrict__ attw_b,
                              const float* __restrict__ proj_w)
{
    int idx = blockIdx.x * blockDim.x + threadIdx.x;
    if (idx < DD * NCAT) {
        int k = idx / NCAT, n = idx % NCAT;
        float w;
        if (n < 256)      w = qkv_w[k * 768 + 512 + n];
        else if (n < 320) w = off_w[k * 64 + (n - 256)];
        else if (n < 352) w = attw_w[k * 32 + (n - 320)];
        else              w = 0.0f;
        __half h, l; split_f16(w, h, l);
        g_w1h[idx] = h; g_w1l[idx] = l;
    }
    int idx2 = idx - DD * NCAT;
    if (idx2 >= 0 && idx2 < DD * DD) {
        __half h, l; split_f16(proj_w[idx2], h, l);
        g_w2h[idx2] = h; g_w2l[idx2] = l;
    }
    if (idx < NCAT) {
        float bv;
        if (idx < 256)      bv = qkv_b[512 + idx];
        else if (idx < 320) bv = off_b[idx - 256];
        else if (idx < 352) bv = attw_b[idx - 320];
        else                bv = 0.0f;
        g_bcat[idx] = bv;
    }
}

// =================== fp16 2-term GEMM (R15-proven structure) ===============
// C[M,Nw] = A_f16[M,256] @ (Bh + Bl) + bias; A single smem image, B hi/lo.
#define A_ROW_B   80
#define B_ROW_B   144
#define SM_A_SZ   10240                     // one image: 128*80
#define SM_B_SZ   4608                      // 32*144
#define G_B_OFF   SM_A_SZ                   // 10240
#define G_STAGE   (SM_A_SZ + 2 * SM_B_SZ)   // 19456
#define G_SMEM    (3 * G_STAGE)             // 58368

__device__ __forceinline__ void f16_gemm_body(const __half* __restrict__ A,
                                              const __half* __restrict__ Bh,
                                              const __half* __restrict__ Bl,
                                              const float* __restrict__ bias,
                                              float* __restrict__ C, int Nw)
{
    extern __shared__ char smem[];
    const uint32_t sm = smem_to_u32(smem);
    const int tid = threadIdx.x;
    const int lane = tid & 31, wid = tid >> 5;
    const int warp_m = wid >> 1, warp_n = wid & 1;
    const int m0 = blockIdx.y * 128, n0 = blockIdx.x * 64;

    // A: 512 chunks of 16B (single image), 2 per thread
    const __half* a_src[2]; uint32_t a_dst[2];
#pragma unroll
    for (int i = 0; i < 2; ++i) {
        int c = tid + i * 256;
        int row = c >> 2, kc = c & 3;
        a_src[i] = A + (size_t)(m0 + row) * DD + kc * 8;
        a_dst[i] = sm + row * A_ROW_B + kc * 16;
    }
    // B: 512 chunks (2 images), 2 per thread
    const __half* b_src[2]; uint32_t b_dst[2];
#pragma unroll
    for (int j = 0; j < 2; ++j) {
        int c = tid + j * 256;
        int mat = c >> 8, cc = c & 255, row = cc >> 3, nc = cc & 7;
        b_src[j] = (mat ? Bl : Bh) + (size_t)row * Nw + n0 + nc * 8;
        b_dst[j] = sm + G_B_OFF + mat * SM_B_SZ + row * B_ROW_B + nc * 16;
    }

    float acc[2][4][4];
#pragma unroll
    for (int mt = 0; mt < 2; ++mt)
#pragma unroll
        for (int nt = 0; nt < 4; ++nt)
#pragma unroll
            for (int e = 0; e < 4; ++e) acc[mt][nt][e] = 0.0f;

    auto prefetch = [&](int s, int buf) {
        uint32_t bo = (uint32_t)buf * G_STAGE;
#pragma unroll
        for (int i = 0; i < 2; ++i) cp_async16(a_dst[i] + bo, a_src[i] + s * 32);
#pragma unroll
        for (int j = 0; j < 2; ++j) cp_async16(b_dst[j] + bo, b_src[j] + (size_t)s * 32 * Nw);
        cp_commit();
    };

    prefetch(0, 0);
    prefetch(1, 1);
    int buf = 0;
    for (int s = 0; s < 8; ++s) {
        if (s < 7) asm volatile("cp.async.wait_group 1;");
        else       asm volatile("cp.async.wait_group 0;");
        __syncthreads();
        if (s + 2 < 8) prefetch(s + 2, (s + 2) % 3);

        uint32_t base = sm + (uint32_t)buf * G_STAGE;
#pragma unroll
        for (int k16 = 0; k16 < 2; ++k16) {
            const int kk = k16 * 16;
            uint32_t ah[2][4];
            const int rA = lane & 15, cA = kk + ((lane >> 4) << 3);
#pragma unroll
            for (int mt = 0; mt < 2; ++mt) {
                uint32_t ad = base + (warp_m * 32 + mt * 16 + rA) * A_ROW_B + cA * 2;
                ldsm_x4(ah[mt], ad);
            }
            uint32_t bh[4][2], bl[4][2];
            const int rB = kk + (lane & 15);
            const int cB = warp_n * 32 + ((lane >> 4) << 3);
#pragma unroll
            for (int ntp = 0; ntp < 2; ++ntp) {
                uint32_t bd = base + G_B_OFF + rB * B_ROW_B + (cB + ntp * 16) * 2;
                uint32_t t4[4];
                ldsm_x4t(t4, bd);
                bh[2 * ntp][0] = t4[0]; bh[2 * ntp][1] = t4[1];
                bh[2 * ntp + 1][0] = t4[2]; bh[2 * ntp + 1][1] = t4[3];
                ldsm_x4t(t4, bd + SM_B_SZ);
                bl[2 * ntp][0] = t4[0]; bl[2 * ntp][1] = t4[1];
                bl[2 * ntp + 1][0] = t4[2]; bl[2 * ntp + 1][1] = t4[3];
            }
            // 2 terms: A*Bh then A*Bl (per-accumulator order preserved)
#pragma unroll
            for (int mt = 0; mt < 2; ++mt)
#pragma unroll
                for (int nt = 0; nt < 4; ++nt)
                    mma_f16(acc[mt][nt], ah[mt], bh[nt]);
#pragma unroll
            for (int mt = 0; mt < 2; ++mt)
#pragma unroll
                for (int nt = 0; nt < 4; ++nt)
                    mma_f16(acc[mt][nt], ah[mt], bl[nt]);
        }
        buf = (buf + 1) % 3;
    }

    const int rbase = m0 + warp_m * 32 + (lane >> 2);
    const int cbase = n0 + warp_n * 32 + (lane & 3) * 2;
#pragma unroll
    for (int mt = 0; mt < 2; ++mt) {
#pragma unroll
        for (int nt = 0; nt < 4; ++nt) {
            int col = cbase + nt * 8;
            float b0 = bias[col], b1 = bias[col + 1];
            float2 v0 = make_float2(acc[mt][nt][0] + b0, acc[mt][nt][1] + b1);
            float2 v1 = make_float2(acc[mt][nt][2] + b0, acc[mt][nt][3] + b1);
            *reinterpret_cast<float2*>(C + (size_t)(rbase + mt * 16) * Nw + col) = v0;
            *reinterpret_cast<float2*>(C + (size_t)(rbase + mt * 16 + 8) * Nw + col) = v1;
        }
    }
}

__global__ __launch_bounds__(256, 2) void gemm1_kernel()
{
    f16_gemm_body(g_xh, g_w1h, g_w1l, g_bcat, g_y, NCAT);
}

__global__ __launch_bounds__(256, 2) void gemm2_kernel(const float* __restrict__ proj_b,
                                                       float* __restrict__ out)
{
    f16_gemm_body(g_mid, g_w2h, g_w2l, proj_b, out, DD);
}

// ---------------- deformable sampling: async window + fused prep (R14) ------
#define PREP_STRIDE 24                       // floats per pixel (16B aligned)
#define SMEM_WIN_SZ (WIN * WIN * HD * 4)     // 51200
#define SMEM_SAMP_SZ (SMEM_WIN_SZ + 256 * PREP_STRIDE * 4)   // 75776

__global__ __launch_bounds__(256) void sample_kernel()
{
    extern __shared__ float vt[];            // window [400][32], then prep [256][24]
    float* prep = vt + WIN * WIN * HD;
    const int tid = threadIdx.x;
    const int lane = tid & 31, wid = tid >> 5;

    const int t = blockIdx.x;
    const int tile = t & 15;
    const int h = (t >> 4) & 7;
    const int b = t >> 7;
    const int tx0 = (tile & 3) * TILE_PX;
    const int ty0 = (tile >> 2) * TILE_PX;

    const uint32_t vt_sm = smem_to_u32(vt);

    // ---- issue async window load: 400 positions x 128B, 8 chunks each ----
    {
        const float* ybase = g_y + (size_t)b * NN * NCAT + h * HD;
#pragma unroll
        for (int it = 0; it < 13; ++it) {
            int c = tid + it * 256;
            if (it == 12 && c >= 3200) break;
            int pos = c >> 3, sub = c & 7;
            int py = pos / WIN, px = pos % WIN;
            int gy = ty0 - 2 + py, gx = tx0 - 2 + px;
            bool valid = (gy >= 0 && gy < 64 && gx >= 0 && gx < 64);
            int gyc = valid ? gy : 0, gxc = valid ? gx : 0;   // clamp (unread if sz=0)
            const float* src = ybase + (size_t)(gyc * 64 + gxc) * NCAT + sub * 4;
            cp_async16_z(vt_sm + (uint32_t)(pos * HD + sub * 4) * 4, src, valid ? 16 : 0);
        }
        cp_commit();
    }

    // ---- lane-parallel prep while window copies fly ----
    {
        int q = wid * 32 + lane;
        int py = q >> 4, px = q & 15;
        int n = (ty0 + py) * 64 + (tx0 + px);
        const float* yrow = g_y + (size_t)(b * NN + n) * NCAT;

        float4 o0 = *reinterpret_cast<const float4*>(yrow + 256 + h * 8);
        float4 o1 = *reinterpret_cast<const float4*>(yrow + 256 + h * 8 + 4);
        float4 av = *reinterpret_cast<const float4*>(yrow + 320 + h * 4);
        float offr[8] = {o0.x, o0.y, o0.z, o0.w, o1.x, o1.y, o1.z, o1.w};
        float aw[4] = {av.x, av.y, av.z, av.w};

        float mx = fmaxf(fmaxf(aw[0], aw[1]), fmaxf(aw[2], aw[3]));
        float s = 0.0f;
#pragma unroll
        for (int p = 0; p < NP; ++p) { aw[p] = __expf(aw[p] - mx); s += aw[p]; }
        float inv = 1.0f / s;

        float pxl = (float)px + 2.0f;
        float pyl = (float)py + 2.0f;

        int offs[4]; float4 w[4];
#pragma unroll
        for (int p = 0; p < NP; ++p) {
            float lgx = pxl + 2.0f * tanhf(offr[2 * p]);
            float lgy = pyl + 2.0f * tanhf(offr[2 * p + 1]);
            float x0f = floorf(lgx), y0f = floorf(lgy);
            float wx1 = lgx - x0f, wy1 = lgy - y0f;
            float wx0 = 1.0f - wx1, wy0 = 1.0f - wy1;
            float ap = aw[p] * inv;
            w[p].x = ap * wx0 * wy0;
            w[p].y = ap * wx1 * wy0;
            w[p].z = ap * wx0 * wy1;
            w[p].w = ap * wx1 * wy1;
            offs[p] = ((int)y0f * WIN + (int)x0f) * HD;
        }
        float* dst = prep + q * PREP_STRIDE;
        *reinterpret_cast<int4*>(dst) = make_int4(offs[0], offs[1], offs[2], offs[3]);
        *reinterpret_cast<float4*>(dst + 4)  = w[0];
        *reinterpret_cast<float4*>(dst + 8)  = w[1];
        *reinterpret_cast<float4*>(dst + 12) = w[2];
        *reinterpret_cast<float4*>(dst + 16) = w[3];
    }

    asm volatile("cp.async.wait_group 0;");
    __syncthreads();

    const float* basep = vt + lane;

    // ---- main loop: warp w handles pixels [32w, 32w+32) ----
#pragma unroll 4
    for (int j = 0; j < 32; ++j) {
        int q = wid * 32 + j;
        const float* pp = prep + q * PREP_STRIDE;
        int4 off  = *reinterpret_cast<const int4*>(pp);
        float4 w0 = *reinterpret_cast<const float4*>(pp + 4);
        float4 w1 = *reinterpret_cast<const float4*>(pp + 8);
        float4 w2 = *reinterpret_cast<const float4*>(pp + 12);
        float4 w3 = *reinterpret_cast<const float4*>(pp + 16);

        const float* c0 = basep + off.x;
        const float* c1 = basep + off.y;
        const float* c2 = basep + off.z;
        const float* c3 = basep + off.w;
        float acc;
        acc  = w0.x * c0[0] + w0.y * c0[HD] + w0.z * c0[WIN * HD] + w0.w * c0[WIN * HD + HD];
        acc += w1.x * c1[0] + w1.y * c1[HD] + w1.z * c1[WIN * HD] + w1.w * c1[WIN * HD + HD];
        acc += w2.x * c2[0] + w2.y * c2[HD] + w2.z * c2[WIN * HD] + w2.w * c2[WIN * HD + HD];
        acc += w3.x * c3[0] + w3.y * c3[HD] + w3.z * c3[WIN * HD] + w3.w * c3[WIN * HD + HD];

        int n = (ty0 + (q >> 4)) * 64 + (tx0 + (q & 15));
        size_t ofs = (size_t)(b * NN + n) * DD + h * HD + lane;
        g_mid[ofs] = __float2half_rn(acc);
    }
}

// ---------------- launch ----------------
extern "C" void kernel_launch(void* const* d_in, const int* in_sizes, int n_in,
                              void* d_out, int out_size)
{
    const float* x      = (const float*)d_in[0];
    const float* qkv_w  = (const float*)d_in[1];
    const float* qkv_b  = (const float*)d_in[2];
    const float* off_w  = (const float*)d_in[3];
    const float* off_b  = (const float*)d_in[4];
    const float* attw_w = (const float*)d_in[5];
    const float* attw_b = (const float*)d_in[6];
    const float* proj_w = (const float*)d_in[7];
    const float* proj_b = (const float*)d_in[8];
    float* out = (float*)d_out;

    cudaFuncSetAttribute(gemm1_kernel, cudaFuncAttributeMaxDynamicSharedMemorySize, G_SMEM);
    cudaFuncSetAttribute(gemm2_kernel, cudaFuncAttributeMaxDynamicSharedMemorySize, G_SMEM);
    cudaFuncSetAttribute(sample_kernel, cudaFuncAttributeMaxDynamicSharedMemorySize, SMEM_SAMP_SZ);

    // 1) pack: x -> fp16 image, w1/w2 -> fp16 hi/lo
    pack_x_kernel<<<(MM * DD / 4 + 255) / 256, 256>>>(x);
    pack_w_kernel<<<(DD * NCAT + DD * DD + 255) / 256, 256>>>(
        qkv_w, qkv_b, off_w, off_b, attw_w, attw_b, proj_w);

    // 2) stage-1 GEMM (fp16 2-term): X[32768,256] @ Wcat[256,384] -> g_y
    gemm1_kernel<<<dim3(NCAT / 64, MM / 128), 256, G_SMEM>>>();

    // 3) deformable sampling (R14-proven core, fp16 output)
    sample_kernel<<<BB * NH * 16, 256, SMEM_SAMP_SZ>>>();

    // 4) output projection (fp16 2-term): mid @ proj_w[256,256] + b -> out
    gemm2_kernel<<<dim3(DD / 64, MM / 128), 256, G_SMEM>>>(proj_b, out);
}

// round 17
// speedup vs baseline: 1.5000x; 1.0875x over previous
#include <cuda_runtime.h>
#include <cuda_bf16.h>
#include <cuda_fp16.h>
#include <cstdint>
#include <math.h>

// Problem constants (fixed shapes from setup_inputs)
#define BB   8
#define NN   4096      // 64*64
#define DD   256
#define NH   8
#define NP   4
#define HD   32
#define MM   (BB*NN)   // 32768 rows
#define NCAT 384       // 256 (v) + 64 (off) + 32 (attw) + 32 pad

#define TILE_PX  16
#define WIN      20                         // 16 + 2*2 halo

// ---------------- scratch (device globals; no allocations allowed) ----------
__device__ __half g_v[(size_t)MM * DD];           // stage-1 v output (fp16)
__device__ float g_oa[(size_t)MM * 128];          // stage-1 off(64)+attw(32)+pad (fp32)
__device__ float g_bcat[NCAT];                    // packed stage-1 bias
__device__ __half g_xh[(size_t)MM * DD];          // x as fp16 (single image)
__device__ __half g_mid[(size_t)MM * DD];         // sampled output as fp16
__device__ __half g_w1h[DD * NCAT];               // [k][n] stage-1 weights fp16 hi
__device__ __half g_w1l[DD * NCAT];               // [k][n] stage-1 weights fp16 lo
__device__ __half g_w2h[DD * DD];                 // [k][n] proj weights fp16 hi
__device__ __half g_w2l[DD * DD];                 // [k][n] proj weights fp16 lo

// =================== helpers ===================
__device__ __forceinline__ uint32_t smem_to_u32(const void* p) {
    uint32_t a;
    asm("{ .reg .u64 t; cvta.to.shared.u64 t, %1; cvt.u32.u64 %0, t; }" : "=r"(a) : "l"(p));
    return a;
}
__device__ __forceinline__ void split_f16(float w, __half& h, __half& l) {
    h = __float2half_rn(w);
    l = __float2half_rn(w - __half2float(h));
}
__device__ __forceinline__ void cp_async16(uint32_t dst, const void* src) {
    asm volatile("{ .reg .u64 g; cvta.to.global.u64 g, %1; cp.async.cg.shared.global [%0], [g], 16; }"
                 :: "r"(dst), "l"(src));
}
// cp.async with dynamic src-size: bytes beyond sz are ZERO-FILLED (sz=0 -> all zeros)
__device__ __forceinline__ void cp_async16_z(uint32_t dst, const void* src, int sz) {
    asm volatile("{ .reg .u64 g; cvta.to.global.u64 g, %1; cp.async.cg.shared.global [%0], [g], 16, %2; }"
                 :: "r"(dst), "l"(src), "r"(sz));
}
__device__ __forceinline__ void cp_commit() {
    asm volatile("cp.async.commit_group;");
}
__device__ __forceinline__ void ldsm_x4(uint32_t (&r)[4], uint32_t addr) {
    asm volatile("ldmatrix.sync.aligned.m8n8.x4.shared.b16 {%0,%1,%2,%3}, [%4];"
                 : "=r"(r[0]), "=r"(r[1]), "=r"(r[2]), "=r"(r[3]) : "r"(addr));
}
__device__ __forceinline__ void ldsm_x4t(uint32_t (&r)[4], uint32_t addr) {
    asm volatile("ldmatrix.sync.aligned.m8n8.x4.trans.shared.b16 {%0,%1,%2,%3}, [%4];"
                 : "=r"(r[0]), "=r"(r[1]), "=r"(r[2]), "=r"(r[3]) : "r"(addr));
}
__device__ __forceinline__ void mma_f16(float (&c)[4], const uint32_t (&a)[4], const uint32_t (&b)[2]) {
    asm volatile("mma.sync.aligned.m16n8k16.row.col.f32.f16.f16.f32 "
                 "{%0,%1,%2,%3}, {%4,%5,%6,%7}, {%8,%9}, {%0,%1,%2,%3};"
                 : "+f"(c[0]), "+f"(c[1]), "+f"(c[2]), "+f"(c[3])
                 : "r"(a[0]), "r"(a[1]), "r"(a[2]), "r"(a[3]), "r"(b[0]), "r"(b[1]));
}

// =================== pack kernel (x + all weights, one launch) ==============
__global__ void pack_all_kernel(const float* __restrict__ x,
                                const float* __restrict__ qkv_w, const float* __restrict__ qkv_b,
                                const float* __restrict__ off_w, const float* __restrict__ off_b,
                                const float* __restrict__ attw_w, const float* __restrict__ attw_b,
                                const float* __restrict__ proj_w)
{
    int idx = blockIdx.x * blockDim.x + threadIdx.x;
    if (idx < MM * DD / 4) {
        float4 v = reinterpret_cast<const float4*>(x)[idx];
        __half2 p0 = make_half2(__float2half_rn(v.x), __float2half_rn(v.y));
        __half2 p1 = make_half2(__float2half_rn(v.z), __float2half_rn(v.w));
        uint2 pk;
        pk.x = *reinterpret_cast<uint32_t*>(&p0);
        pk.y = *reinterpret_cast<uint32_t*>(&p1);
        reinterpret_cast<uint2*>(g_xh)[idx] = pk;
    }
    if (idx < DD * NCAT) {
        int k = idx / NCAT, n = idx % NCAT;
        float w;
        if (n < 256)      w = qkv_w[k * 768 + 512 + n];
        else if (n < 320) w = off_w[k * 64 + (n - 256)];
        else if (n < 352) w = attw_w[k * 32 + (n - 320)];
        else              w = 0.0f;
        __half h, l; split_f16(w, h, l);
        g_w1h[idx] = h; g_w1l[idx] = l;
    }
    int idx2 = idx - DD * NCAT;
    if (idx2 >= 0 && idx2 < DD * DD) {
        __half h, l; split_f16(proj_w[idx2], h, l);
        g_w2h[idx2] = h; g_w2l[idx2] = l;
    }
    if (idx < NCAT) {
        float bv;
        if (idx < 256)      bv = qkv_b[512 + idx];
        else if (idx < 320) bv = off_b[idx - 256];
        else if (idx < 352) bv = attw_b[idx - 320];
        else                bv = 0.0f;
        g_bcat[idx] = bv;
    }
}

// =================== fp16 2-term GEMM (R16-proven structure) ===============
// C[M,Nw] = A_f16[M,256] @ (Bh + Bl) + bias; A single smem image, B hi/lo.
// SPLIT=true (gemm1): v cols (n0<256) -> g_v fp16; off/attw cols -> g_oa fp32.
#define A_ROW_B   80
#define B_ROW_B   144
#define SM_A_SZ   10240                     // one image: 128*80
#define SM_B_SZ   4608                      // 32*144
#define G_B_OFF   SM_A_SZ                   // 10240
#define G_STAGE   (SM_A_SZ + 2 * SM_B_SZ)   // 19456
#define G_SMEM    (3 * G_STAGE)             // 58368

template <bool SPLIT>
__device__ __forceinline__ void f16_gemm_body(const __half* __restrict__ A,
                                              const __half* __restrict__ Bh,
                                              const __half* __restrict__ Bl,
                                              const float* __restrict__ bias,
                                              float* __restrict__ C, int Nw)
{
    extern __shared__ char smem[];
    const uint32_t sm = smem_to_u32(smem);
    const int tid = threadIdx.x;
    const int lane = tid & 31, wid = tid >> 5;
    const int warp_m = wid >> 1, warp_n = wid & 1;
    const int m0 = blockIdx.y * 128, n0 = blockIdx.x * 64;

    const __half* a_src[2]; uint32_t a_dst[2];
#pragma unroll
    for (int i = 0; i < 2; ++i) {
        int c = tid + i * 256;
        int row = c >> 2, kc = c & 3;
        a_src[i] = A + (size_t)(m0 + row) * DD + kc * 8;
        a_dst[i] = sm + row * A_ROW_B + kc * 16;
    }
    const __half* b_src[2]; uint32_t b_dst[2];
#pragma unroll
    for (int j = 0; j < 2; ++j) {
        int c = tid + j * 256;
        int mat = c >> 8, cc = c & 255, row = cc >> 3, nc = cc & 7;
        b_src[j] = (mat ? Bl : Bh) + (size_t)row * Nw + n0 + nc * 8;
        b_dst[j] = sm + G_B_OFF + mat * SM_B_SZ + row * B_ROW_B + nc * 16;
    }

    float acc[2][4][4];
#pragma unroll
    for (int mt = 0; mt < 2; ++mt)
#pragma unroll
        for (int nt = 0; nt < 4; ++nt)
#pragma unroll
            for (int e = 0; e < 4; ++e) acc[mt][nt][e] = 0.0f;

    auto prefetch = [&](int s, int buf) {
        uint32_t bo = (uint32_t)buf * G_STAGE;
#pragma unroll
        for (int i = 0; i < 2; ++i) cp_async16(a_dst[i] + bo, a_src[i] + s * 32);
#pragma unroll
        for (int j = 0; j < 2; ++j) cp_async16(b_dst[j] + bo, b_src[j] + (size_t)s * 32 * Nw);
        cp_commit();
    };

    prefetch(0, 0);
    prefetch(1, 1);
    int buf = 0;
    for (int s = 0; s < 8; ++s) {
        if (s < 7) asm volatile("cp.async.wait_group 1;");
        else       asm volatile("cp.async.wait_group 0;");
        __syncthreads();
        if (s + 2 < 8) prefetch(s + 2, (s + 2) % 3);

        uint32_t base = sm + (uint32_t)buf * G_STAGE;
#pragma unroll
        for (int k16 = 0; k16 < 2; ++k16) {
            const int kk = k16 * 16;
            uint32_t ah[2][4];
            const int rA = lane & 15, cA = kk + ((lane >> 4) << 3);
#pragma unroll
            for (int mt = 0; mt < 2; ++mt) {
                uint32_t ad = base + (warp_m * 32 + mt * 16 + rA) * A_ROW_B + cA * 2;
                ldsm_x4(ah[mt], ad);
            }
            uint32_t bh[4][2], bl[4][2];
            const int rB = kk + (lane & 15);
            const int cB = warp_n * 32 + ((lane >> 4) << 3);
#pragma unroll
            for (int ntp = 0; ntp < 2; ++ntp) {
                uint32_t bd = base + G_B_OFF + rB * B_ROW_B + (cB + ntp * 16) * 2;
                uint32_t t4[4];
                ldsm_x4t(t4, bd);
                bh[2 * ntp][0] = t4[0]; bh[2 * ntp][1] = t4[1];
                bh[2 * ntp + 1][0] = t4[2]; bh[2 * ntp + 1][1] = t4[3];
                ldsm_x4t(t4, bd + SM_B_SZ);
                bl[2 * ntp][0] = t4[0]; bl[2 * ntp][1] = t4[1];
                bl[2 * ntp + 1][0] = t4[2]; bl[2 * ntp + 1][1] = t4[3];
            }
#pragma unroll
            for (int mt = 0; mt < 2; ++mt)
#pragma unroll
                for (int nt = 0; nt < 4; ++nt)
                    mma_f16(acc[mt][nt], ah[mt], bh[nt]);
#pragma unroll
            for (int mt = 0; mt < 2; ++mt)
#pragma unroll
                for (int nt = 0; nt < 4; ++nt)
                    mma_f16(acc[mt][nt], ah[mt], bl[nt]);
        }
        buf = (buf + 1) % 3;
    }

    const int rbase = m0 + warp_m * 32 + (lane >> 2);
    const int cbase = n0 + warp_n * 32 + (lane & 3) * 2;
    if (SPLIT) {
        if (n0 < 256) {
            // v columns -> fp16 image
#pragma unroll
            for (int mt = 0; mt < 2; ++mt) {
#pragma unroll
                for (int nt = 0; nt < 4; ++nt) {
                    int col = cbase + nt * 8;
                    float b0 = bias[col], b1 = bias[col + 1];
                    __half2 h0 = __floats2half2_rn(acc[mt][nt][0] + b0, acc[mt][nt][1] + b1);
                    __half2 h1 = __floats2half2_rn(acc[mt][nt][2] + b0, acc[mt][nt][3] + b1);
                    *reinterpret_cast<__half2*>(g_v + (size_t)(rbase + mt * 16) * DD + col) = h0;
                    *reinterpret_cast<__half2*>(g_v + (size_t)(rbase + mt * 16 + 8) * DD + col) = h1;
                }
            }
        } else {
            // off/attw columns -> compact fp32
#pragma unroll
            for (int mt = 0; mt < 2; ++mt) {
#pragma unroll
                for (int nt = 0; nt < 4; ++nt) {
                    int col = cbase + nt * 8;
                    float b0 = bias[col], b1 = bias[col + 1];
                    int cc = col - 256;
                    float2 v0 = make_float2(acc[mt][nt][0] + b0, acc[mt][nt][1] + b1);
                    float2 v1 = make_float2(acc[mt][nt][2] + b0, acc[mt][nt][3] + b1);
                    *reinterpret_cast<float2*>(g_oa + (size_t)(rbase + mt * 16) * 128 + cc) = v0;
                    *reinterpret_cast<float2*>(g_oa + (size_t)(rbase + mt * 16 + 8) * 128 + cc) = v1;
                }
            }
        }
    } else {
#pragma unroll
        for (int mt = 0; mt < 2; ++mt) {
#pragma unroll
            for (int nt = 0; nt < 4; ++nt) {
                int col = cbase + nt * 8;
                float b0 = bias[col], b1 = bias[col + 1];
                float2 v0 = make_float2(acc[mt][nt][0] + b0, acc[mt][nt][1] + b1);
                float2 v1 = make_float2(acc[mt][nt][2] + b0, acc[mt][nt][3] + b1);
                *reinterpret_cast<float2*>(C + (size_t)(rbase + mt * 16) * Nw + col) = v0;
                *reinterpret_cast<float2*>(C + (size_t)(rbase + mt * 16 + 8) * Nw + col) = v1;
            }
        }
    }
}

__global__ __launch_bounds__(256, 2) void gemm1_kernel()
{
    f16_gemm_body<true>(g_xh, g_w1h, g_w1l, g_bcat, nullptr, NCAT);
}

__global__ __launch_bounds__(256, 2) void gemm2_kernel(const float* __restrict__ proj_b,
                                                       float* __restrict__ out)
{
    f16_gemm_body<false>(g_mid, g_w2h, g_w2l, proj_b, out, DD);
}

// ---------------- deformable sampling: fp16 window, 4 CTAs/SM ---------------
// Window now fp16 (25.6KB): cp.async 64B/position; gather = LDS.U16 + cvt.
#define PREP_STRIDE 24                       // floats per pixel (16B aligned)
#define SMEM_WIN_SZ (WIN * WIN * HD * 2)     // 25600 (fp16)
#define SMEM_SAMP_SZ (SMEM_WIN_SZ + 256 * PREP_STRIDE * 4)   // 50176

__global__ __launch_bounds__(256) void sample_kernel()
{
    extern __shared__ char smem_raw[];
    __half* vt = reinterpret_cast<__half*>(smem_raw);          // [400][32] fp16
    float* prep = reinterpret_cast<float*>(smem_raw + SMEM_WIN_SZ);  // [256][24]
    const int tid = threadIdx.x;
    const int lane = tid & 31, wid = tid >> 5;

    const int t = blockIdx.x;
    const int tile = t & 15;
    const int h = (t >> 4) & 7;
    const int b = t >> 7;
    const int tx0 = (tile & 3) * TILE_PX;
    const int ty0 = (tile >> 2) * TILE_PX;

    const uint32_t vt_sm = smem_to_u32(vt);

    // ---- issue async window load: 400 positions x 64B (fp16), 4 chunks each -
    {
        const __half* vbase = g_v + h * HD;
        // 1600 chunks of 16B
#pragma unroll
        for (int it = 0; it < 7; ++it) {
            int c = tid + it * 256;
            if (it == 6 && c >= 1600) break;
            int pos = c >> 2, sub = c & 3;
            int py = pos / WIN, px = pos % WIN;
            int gy = ty0 - 2 + py, gx = tx0 - 2 + px;
            bool valid = (gy >= 0 && gy < 64 && gx >= 0 && gx < 64);
            int gyc = valid ? gy : 0, gxc = valid ? gx : 0;   // clamp (unread if sz=0)
            const __half* src = vbase + (size_t)(b * NN + gyc * 64 + gxc) * DD + sub * 8;
            cp_async16_z(vt_sm + (uint32_t)(pos * HD + sub * 8) * 2, src, valid ? 16 : 0);
        }
        cp_commit();
    }

    // ---- lane-parallel prep while window copies fly ----
    {
        int q = wid * 32 + lane;
        int py = q >> 4, px = q & 15;
        int n = (ty0 + py) * 64 + (tx0 + px);
        const float* yrow = g_oa + (size_t)(b * NN + n) * 128;

        float4 o0 = *reinterpret_cast<const float4*>(yrow + h * 8);
        float4 o1 = *reinterpret_cast<const float4*>(yrow + h * 8 + 4);
        float4 av = *reinterpret_cast<const float4*>(yrow + 64 + h * 4);
        float offr[8] = {o0.x, o0.y, o0.z, o0.w, o1.x, o1.y, o1.z, o1.w};
        float aw[4] = {av.x, av.y, av.z, av.w};

        float mx = fmaxf(fmaxf(aw[0], aw[1]), fmaxf(aw[2], aw[3]));
        float s = 0.0f;
#pragma unroll
        for (int p = 0; p < NP; ++p) { aw[p] = __expf(aw[p] - mx); s += aw[p]; }
        float inv = 1.0f / s;

        float pxl = (float)px + 2.0f;
        float pyl = (float)py + 2.0f;

        int offs[4]; float4 w[4];
#pragma unroll
        for (int p = 0; p < NP; ++p) {
            float lgx = pxl + 2.0f * tanhf(offr[2 * p]);
            float lgy = pyl + 2.0f * tanhf(offr[2 * p + 1]);
            float x0f = floorf(lgx), y0f = floorf(lgy);
            float wx1 = lgx - x0f, wy1 = lgy - y0f;
            float wx0 = 1.0f - wx1, wy0 = 1.0f - wy1;
            float ap = aw[p] * inv;
            w[p].x = ap * wx0 * wy0;
            w[p].y = ap * wx1 * wy0;
            w[p].z = ap * wx0 * wy1;
            w[p].w = ap * wx1 * wy1;
            offs[p] = ((int)y0f * WIN + (int)x0f) * HD;
        }
        float* dst = prep + q * PREP_STRIDE;
        *reinterpret_cast<int4*>(dst) = make_int4(offs[0], offs[1], offs[2], offs[3]);
        *reinterpret_cast<float4*>(dst + 4)  = w[0];
        *reinterpret_cast<float4*>(dst + 8)  = w[1];
        *reinterpret_cast<float4*>(dst + 12) = w[2];
        *reinterpret_cast<float4*>(dst + 16) = w[3];
    }

    asm volatile("cp.async.wait_group 0;");
    __syncthreads();

    const __half* basep = vt + lane;

    // ---- main loop: warp w handles pixels [32w, 32w+32) ----
#pragma unroll 4
    for (int j = 0; j < 32; ++j) {
        int q = wid * 32 + j;
        const float* pp = prep + q * PREP_STRIDE;
        int4 off  = *reinterpret_cast<const int4*>(pp);
        float4 w0 = *reinterpret_cast<const float4*>(pp + 4);
        float4 w1 = *reinterpret_cast<const float4*>(pp + 8);
        float4 w2 = *reinterpret_cast<const float4*>(pp + 12);
        float4 w3 = *reinterpret_cast<const float4*>(pp + 16);

        const __half* c0 = basep + off.x;
        const __half* c1 = basep + off.y;
        const __half* c2 = basep + off.z;
        const __half* c3 = basep + off.w;
        float acc;
        acc  = w0.x * __half2float(c0[0]) + w0.y * __half2float(c0[HD])
             + w0.z * __half2float(c0[WIN * HD]) + w0.w * __half2float(c0[WIN * HD + HD]);
        acc += w1.x * __half2float(c1[0]) + w1.y * __half2float(c1[HD])
             + w1.z * __half2float(c1[WIN * HD]) + w1.w * __half2float(c1[WIN * HD + HD]);
        acc += w2.x * __half2float(c2[0]) + w2.y * __half2float(c2[HD])
             + w2.z * __half2float(c2[WIN * HD]) + w2.w * __half2float(c2[WIN * HD + HD]);
        acc += w3.x * __half2float(c3[0]) + w3.y * __half2float(c3[HD])
             + w3.z * __half2float(c3[WIN * HD]) + w3.w * __half2float(c3[WIN * HD + HD]);

        int n = (ty0 + (q >> 4)) * 64 + (tx0 + (q & 15));
        size_t ofs = (size_t)(b * NN + n) * DD + h * HD + lane;
        g_mid[ofs] = __float2half_rn(acc);
    }
}

// ---------------- launch ----------------
extern "C" void kernel_launch(void* const* d_in, const int* in_sizes, int n_in,
                              void* d_out, int out_size)
{
    const float* x      = (const float*)d_in[0];
    const float* qkv_w  = (const float*)d_in[1];
    const float* qkv_b  = (const float*)d_in[2];
    const float* off_w  = (const float*)d_in[3];
    const float* off_b  = (const float*)d_in[4];
    const float* attw_w = (const float*)d_in[5];
    const float* attw_b = (const float*)d_in[6];
    const float* proj_w = (const float*)d_in[7];
    const float* proj_b = (const float*)d_in[8];
    float* out = (float*)d_out;

    cudaFuncSetAttribute(gemm1_kernel, cudaFuncAttributeMaxDynamicSharedMemorySize, G_SMEM);
    cudaFuncSetAttribute(gemm2_kernel, cudaFuncAttributeMaxDynamicSharedMemorySize, G_SMEM);
    cudaFuncSetAttribute(sample_kernel, cudaFuncAttributeMaxDynamicSharedMemorySize, SMEM_SAMP_SZ);

    // 1) pack: x -> fp16 image, w1/w2 -> fp16 hi/lo (single launch)
    pack_all_kernel<<<(MM * DD / 4 + 255) / 256, 256>>>(
        x, qkv_w, qkv_b, off_w, off_b, attw_w, attw_b, proj_w);

    // 2) stage-1 GEMM (fp16 2-term): split epilogue -> g_v (fp16) + g_oa (fp32)
    gemm1_kernel<<<dim3(NCAT / 64, MM / 128), 256, G_SMEM>>>();

    // 3) deformable sampling: fp16 window, 4 CTAs/SM
    sample_kernel<<<BB * NH * 16, 256, SMEM_SAMP_SZ>>>();

    // 4) output projection (fp16 2-term): mid @ proj_w[256,256] + b -> out
    gemm2_kernel<<<dim3(DD / 64, MM / 128), 256, G_SMEM>>>(proj_b, out);
}